// round 4
// baseline (speedup 1.0000x reference)
#include <cuda_runtime.h>
#include <cuda_bf16.h>
#include <cstdint>

#define BSZ 8192
#define DD  512
#define CC  512
#define MT  128
#define NT  256
#define NSTG 8                       // K chunks of 64 bf16

// ---- device scratch ----
__device__ __nv_bfloat16 g_xh[BSZ * DD];
__device__ __nv_bfloat16 g_xl[BSZ * DD];
__device__ __nv_bfloat16 g_ch[CC * DD];
__device__ __nv_bfloat16 g_cl[CC * DD];
__device__ float g_xnorm[BSZ];
__device__ float g_cnorm[CC];
__device__ int   g_present[CC];      // zero-init; only 1s written (idempotent across replays)
__device__ float g_minp[2 * BSZ];
__device__ float g_ownp[BSZ];
__device__ float g_rpart[64];
__device__ int   g_rcount;           // zero-init; reset by last block each call

// ---- smem layout (bytes) ----
#define SM_TILE 2048
#define OFF_AH  0
#define OFF_AL  16384
#define OFF_CH  32768
#define OFF_CL  65536
#define STG_B   98304
#define SMEM_BYTES (SM_TILE + 2 * STG_B)   // 198656

static __device__ __forceinline__ uint32_t s2u(const void* p) {
    uint32_t a;
    asm("{ .reg .u64 t; cvta.to.shared.u64 t, %1; cvt.u32.u64 %0, t; }" : "=r"(a) : "l"(p));
    return a;
}
static __device__ __forceinline__ void cp16(uint32_t dst, const void* src) {
    asm volatile("cp.async.cg.shared.global [%0], [%1], 16;" :: "r"(dst), "l"(src));
}
#define LDSM4(r0, r1, r2, r3, addr)                                             \
    asm volatile("ldmatrix.sync.aligned.m8n8.x4.shared.b16 {%0,%1,%2,%3}, [%4];" \
                 : "=r"(r0), "=r"(r1), "=r"(r2), "=r"(r3) : "r"(addr))
#define MMA(d, a, b0, b1)                                                        \
    asm volatile("mma.sync.aligned.m16n8k16.row.col.f32.bf16.bf16.f32 "          \
                 "{%0,%1,%2,%3},{%4,%5,%6,%7},{%8,%9},{%0,%1,%2,%3};"            \
                 : "+f"((d)[0]), "+f"((d)[1]), "+f"((d)[2]), "+f"((d)[3])        \
                 : "r"((a)[0]), "r"((a)[1]), "r"((a)[2]), "r"((a)[3]),           \
                   "r"(b0), "r"(b1))

// ---------------------------------------------------------------------------
// prep: f32 -> bf16 hi/lo split + row norms + class presence. One warp/row.
// ---------------------------------------------------------------------------
__global__ void prep_kernel(const float* __restrict__ X, const float* __restrict__ CT,
                            const int* __restrict__ T) {
    int row  = blockIdx.x * 8 + (threadIdx.x >> 5);
    int lane = threadIdx.x & 31;
    const float* src;
    __nv_bfloat16 *dh, *dl;
    float* nrm;
    size_t rb;
    if (row < CC) {
        src = CT + (size_t)row * DD; dh = g_ch; dl = g_cl; nrm = g_cnorm + row;
        rb = (size_t)row * DD;
    } else {
        int r = row - CC;
        if (r >= BSZ) return;
        src = X + (size_t)r * DD; dh = g_xh; dl = g_xl; nrm = g_xnorm + r;
        rb = (size_t)r * DD;
        if (lane == 0) g_present[T[r]] = 1;
    }
    float s = 0.f;
    const float4* p4 = (const float4*)src;
#pragma unroll
    for (int i = 0; i < 4; i++) {
        float4 v = p4[lane + 32 * i];
        s = fmaf(v.x, v.x, s); s = fmaf(v.y, v.y, s);
        s = fmaf(v.z, v.z, s); s = fmaf(v.w, v.w, s);
        __nv_bfloat16 hx = __float2bfloat16(v.x), hy = __float2bfloat16(v.y);
        __nv_bfloat16 hz = __float2bfloat16(v.z), hw = __float2bfloat16(v.w);
        __nv_bfloat16 lx = __float2bfloat16(v.x - __bfloat162float(hx));
        __nv_bfloat16 ly = __float2bfloat16(v.y - __bfloat162float(hy));
        __nv_bfloat16 lz = __float2bfloat16(v.z - __bfloat162float(hz));
        __nv_bfloat16 lw = __float2bfloat16(v.w - __bfloat162float(hw));
        uint2 hv, lv;
        hv.x = ((uint32_t)__bfloat16_as_ushort(hy) << 16) | __bfloat16_as_ushort(hx);
        hv.y = ((uint32_t)__bfloat16_as_ushort(hw) << 16) | __bfloat16_as_ushort(hz);
        lv.x = ((uint32_t)__bfloat16_as_ushort(ly) << 16) | __bfloat16_as_ushort(lx);
        lv.y = ((uint32_t)__bfloat16_as_ushort(lw) << 16) | __bfloat16_as_ushort(lz);
        size_t eo = rb + (size_t)(lane + 32 * i) * 4;
        *(uint2*)(dh + eo) = hv;
        *(uint2*)(dl + eo) = lv;
    }
#pragma unroll
    for (int o = 16; o > 0; o >>= 1) s += __shfl_xor_sync(0xffffffffu, s, o);
    if (lane == 0) *nrm = s;
}

// ---------------------------------------------------------------------------
// main: M128 x N256 bf16x3 HMMA GEMM + fused hardest-pos/neg epilogue.
// MMA order keeps same-accumulator reuse distance at 8 issues (RAW-stall free).
// ---------------------------------------------------------------------------
__global__ __launch_bounds__(512, 1) void main_kernel(const int* __restrict__ T) {
    extern __shared__ char smem[];
    const uint32_t sb = s2u(smem);
    const int tid = threadIdx.x, lane = tid & 31, wid = tid >> 5;
    const int wr = wid >> 2, wc = wid & 3;
    const int mtile = blockIdx.x >> 1, nh = blockIdx.x & 1;
    const float INF = __int_as_float(0x7f800000);

    float* cn = (float*)smem;              // 256 floats
    int*   tg = (int*)(smem + 1024);       // 128 ints

    for (int i = tid; i < NT; i += 512) {
        int c = nh * NT + i;
        cn[i] = g_present[c] ? g_cnorm[c] : INF;
    }
    if (tid < MT) tg[tid] = T[mtile * MT + tid];

    // ---- cp.async stage loader: 768 rows x 128B, 12 x 16B chunks per thread ----
    const int trow_q = tid >> 3;           // 0..63 row-within-64 band
    const int tq     = tid & 7;            // 16B chunk within row
#define PREFETCH(ST)                                                              \
    do {                                                                          \
        const int st_ = (ST);                                                     \
        const uint32_t dstb_ = sb + SM_TILE + (uint32_t)(st_ & 1) * STG_B;        \
        _Pragma("unroll")                                                         \
        for (int i_ = 0; i_ < 12; i_++) {                                         \
            int row_ = i_ * 64 + trow_q;                                          \
            uint32_t off_ = (uint32_t)(row_ * 128 + tq * 16);                     \
            off_ ^= ((off_ >> 3) & 0x70);                                         \
            const __nv_bfloat16* s_;                                              \
            if (row_ < 128)      s_ = g_xh + (size_t)(mtile * MT + row_) * DD;    \
            else if (row_ < 256) s_ = g_xl + (size_t)(mtile * MT + row_ - 128) * DD; \
            else if (row_ < 512) s_ = g_ch + (size_t)(nh * NT + row_ - 256) * DD; \
            else                 s_ = g_cl + (size_t)(nh * NT + row_ - 512) * DD; \
            cp16(dstb_ + off_, s_ + st_ * 64 + tq * 8);                           \
        }                                                                         \
        asm volatile("cp.async.commit_group;");                                   \
    } while (0)

    PREFETCH(0);
    PREFETCH(1);

    float acc[2][8][4];
#pragma unroll
    for (int a = 0; a < 2; a++)
#pragma unroll
        for (int b = 0; b < 8; b++)
#pragma unroll
            for (int e = 0; e < 4; e++) acc[a][b][e] = 0.f;

    // fragment address components
    const int rA       = wr * 32 + (lane & 15);
    const uint32_t swz = (uint32_t)(lane & 7) << 4;        // swizzle XOR (row&7)<<4
    const uint32_t kA  = (uint32_t)(lane >> 4) << 4;       // A: 0/16B k offset
    const uint32_t kB  = (uint32_t)((lane >> 3) & 1) << 4; // B: 0/16B k offset
    const int nB       = ((lane >> 4) << 3) + (lane & 7);  // B row pattern 0..15

    for (int kt = 0; kt < NSTG; kt++) {
        if (kt == NSTG - 1) asm volatile("cp.async.wait_group 0;");
        else                asm volatile("cp.async.wait_group 1;");
        __syncthreads();

        const uint32_t tb   = sb + SM_TILE + (uint32_t)(kt & 1) * STG_B;
        const uint32_t aAh0 = tb + OFF_AH + (uint32_t)rA * 128;
        const uint32_t aAl0 = tb + OFF_AL + (uint32_t)rA * 128;

#pragma unroll
        for (int kk = 0; kk < 4; kk++) {
            const uint32_t ka = ((uint32_t)(kk * 32) + kA) ^ swz;
            const uint32_t kb = ((uint32_t)(kk * 32) + kB) ^ swz;
            uint32_t ah[2][4], al[2][4];
            LDSM4(ah[0][0], ah[0][1], ah[0][2], ah[0][3], aAh0 + ka);
            LDSM4(ah[1][0], ah[1][1], ah[1][2], ah[1][3], aAh0 + 16 * 128 + ka);
            LDSM4(al[0][0], al[0][1], al[0][2], al[0][3], aAl0 + ka);
            LDSM4(al[1][0], al[1][1], al[1][2], al[1][3], aAl0 + 16 * 128 + ka);
#pragma unroll
            for (int h = 0; h < 2; h++) {
                const uint32_t nbase = (uint32_t)(wc * 64 + h * 32 + nB) * 128;
                uint32_t bh0[4], bh1[4], bl0[4], bl1[4];
                LDSM4(bh0[0], bh0[1], bh0[2], bh0[3], tb + OFF_CH + nbase + kb);
                LDSM4(bh1[0], bh1[1], bh1[2], bh1[3], tb + OFF_CH + nbase + 16 * 128 + kb);
                LDSM4(bl0[0], bl0[1], bl0[2], bl0[3], tb + OFF_CL + nbase + kb);
                LDSM4(bl1[0], bl1[1], bl1[2], bl1[3], tb + OFF_CL + nbase + 16 * 128 + kb);
                // --- ah x B-hi (mb0 then mb1): 8 MMAs ---
                MMA(acc[0][h * 4 + 0], ah[0], bh0[0], bh0[1]);
                MMA(acc[0][h * 4 + 1], ah[0], bh0[2], bh0[3]);
                MMA(acc[0][h * 4 + 2], ah[0], bh1[0], bh1[1]);
                MMA(acc[0][h * 4 + 3], ah[0], bh1[2], bh1[3]);
                MMA(acc[1][h * 4 + 0], ah[1], bh0[0], bh0[1]);
                MMA(acc[1][h * 4 + 1], ah[1], bh0[2], bh0[3]);
                MMA(acc[1][h * 4 + 2], ah[1], bh1[0], bh1[1]);
                MMA(acc[1][h * 4 + 3], ah[1], bh1[2], bh1[3]);
                // --- al x B-hi: same acc revisited at distance 8 issues ---
                MMA(acc[0][h * 4 + 0], al[0], bh0[0], bh0[1]);
                MMA(acc[0][h * 4 + 1], al[0], bh0[2], bh0[3]);
                MMA(acc[0][h * 4 + 2], al[0], bh1[0], bh1[1]);
                MMA(acc[0][h * 4 + 3], al[0], bh1[2], bh1[3]);
                MMA(acc[1][h * 4 + 0], al[1], bh0[0], bh0[1]);
                MMA(acc[1][h * 4 + 1], al[1], bh0[2], bh0[3]);
                MMA(acc[1][h * 4 + 2], al[1], bh1[0], bh1[1]);
                MMA(acc[1][h * 4 + 3], al[1], bh1[2], bh1[3]);
                // --- ah x B-lo: distance 8 again ---
                MMA(acc[0][h * 4 + 0], ah[0], bl0[0], bl0[1]);
                MMA(acc[0][h * 4 + 1], ah[0], bl0[2], bl0[3]);
                MMA(acc[0][h * 4 + 2], ah[0], bl1[0], bl1[1]);
                MMA(acc[0][h * 4 + 3], ah[0], bl1[2], bl1[3]);
                MMA(acc[1][h * 4 + 0], ah[1], bl0[0], bl0[1]);
                MMA(acc[1][h * 4 + 1], ah[1], bl0[2], bl0[3]);
                MMA(acc[1][h * 4 + 2], ah[1], bl1[0], bl1[1]);
                MMA(acc[1][h * 4 + 3], ah[1], bl1[2], bl1[3]);
            }
        }
        __syncthreads();
        if (kt + 2 < NSTG) PREFETCH(kt + 2);
    }

    // ---- epilogue ----
    __syncthreads();                       // tiles now reusable as scratch
    float* red = (float*)(smem + SM_TILE);             // 128 x 4 floats
    float* own = (float*)(smem + SM_TILE + 2048);      // 128 floats

    float rmin[2][2];
#pragma unroll
    for (int mb = 0; mb < 2; mb++) { rmin[mb][0] = INF; rmin[mb][1] = INF; }

#pragma unroll
    for (int mb = 0; mb < 2; mb++)
#pragma unroll
        for (int j = 0; j < 8; j++) {
            const int colb = wc * 64 + (j >> 2) * 32 + (j & 3) * 8 + (lane & 3) * 2;
#pragma unroll
            for (int e = 0; e < 4; e++) {
                const int cl = colb + (e & 1);
                const int lr = wr * 32 + mb * 16 + ((e >> 1) << 3) + (lane >> 2);
                const float v = fmaf(-2.f, acc[mb][j][e], cn[cl]);
                const int oc = tg[lr] - nh * NT;
                if (cl == oc) own[lr] = v;
                else          rmin[mb][e >> 1] = fminf(rmin[mb][e >> 1], v);
            }
        }
#pragma unroll
    for (int mb = 0; mb < 2; mb++)
#pragma unroll
        for (int rr = 0; rr < 2; rr++) {
            float m = rmin[mb][rr];
            m = fminf(m, __shfl_xor_sync(0xffffffffu, m, 1));
            m = fminf(m, __shfl_xor_sync(0xffffffffu, m, 2));
            if ((lane & 3) == 0)
                red[(wr * 32 + mb * 16 + rr * 8 + (lane >> 2)) * 4 + wc] = m;
        }
    __syncthreads();

    if (tid < MT) {
        const int r = tid;
        float m = fminf(fminf(red[r * 4 + 0], red[r * 4 + 1]),
                        fminf(red[r * 4 + 2], red[r * 4 + 3]));
        const int grow = mtile * MT + r;
        g_minp[nh * BSZ + grow] = m;
        const int oc = tg[r] - nh * NT;
        if (oc >= 0 && oc < NT) g_ownp[grow] = own[r];
    }
#undef PREFETCH
}

// ---------------------------------------------------------------------------
// reduce + fused finish (atomic last-block pattern; deterministic, replay-safe)
// ---------------------------------------------------------------------------
__global__ void reduce_kernel(float* out, int out_size) {
    const int row = blockIdx.x * 256 + threadIdx.x;
    const int lane = threadIdx.x & 31, w = threadIdx.x >> 5;
    float mn  = fminf(g_minp[row], g_minp[BSZ + row]);
    float xn  = g_xnorm[row];
    float dap = sqrtf(fmaxf(xn + g_ownp[row], 1e-12f));
    float dan = sqrtf(fmaxf(xn + mn, 1e-12f));
    float li = fmaxf(0.f, dap - dan + 1.f);
    float pi = (dan > dap) ? 1.f : 0.f;
#pragma unroll
    for (int o = 16; o > 0; o >>= 1) {
        li += __shfl_xor_sync(0xffffffffu, li, o);
        pi += __shfl_xor_sync(0xffffffffu, pi, o);
    }
    __shared__ float sl[8], sp[8];
    __shared__ int slast;
    if (lane == 0) { sl[w] = li; sp[w] = pi; }
    __syncthreads();
    if (threadIdx.x == 0) {
        float a = 0.f, b = 0.f;
#pragma unroll
        for (int i = 0; i < 8; i++) { a += sl[i]; b += sp[i]; }
        g_rpart[2 * blockIdx.x]     = a;
        g_rpart[2 * blockIdx.x + 1] = b;
        __threadfence();
        slast = (atomicAdd(&g_rcount, 1) == (int)gridDim.x - 1);
    }
    __syncthreads();
    if (slast && threadIdx.x == 0) {
        float a = 0.f, b = 0.f;
        for (int i = 0; i < (int)gridDim.x; i++) {
            a += g_rpart[2 * i];
            b += g_rpart[2 * i + 1];
        }
        out[0] = a / (float)BSZ;
        if (out_size > 1) out[1] = b / (float)BSZ;
        g_rcount = 0;                 // reset for next graph replay
    }
}

// ---------------------------------------------------------------------------
extern "C" void kernel_launch(void* const* d_in, const int* in_sizes, int n_in,
                              void* d_out, int out_size) {
    const float* X  = nullptr;
    const float* CT = nullptr;
    const int*   T  = nullptr;
    for (int i = 0; i < n_in; i++) {
        if (in_sizes[i] == BSZ * DD)     X  = (const float*)d_in[i];
        else if (in_sizes[i] == CC * DD) CT = (const float*)d_in[i];
        else if (in_sizes[i] == BSZ)     T  = (const int*)d_in[i];
    }
    cudaFuncSetAttribute(main_kernel,
                         cudaFuncAttributeMaxDynamicSharedMemorySize, SMEM_BYTES);

    prep_kernel<<<(CC + BSZ) / 8, 256>>>(X, CT, T);
    main_kernel<<<2 * (BSZ / MT), 512, SMEM_BYTES>>>(T);
    reduce_kernel<<<BSZ / 256, 256>>>((float*)d_out, out_size);
}

// round 5
// speedup vs baseline: 1.4915x; 1.4915x over previous
#include <cuda_runtime.h>
#include <cuda_bf16.h>
#include <cstdint>

#define BSZ 8192
#define DD  512
#define CC  512
#define MT  128
#define NT  256
#define NSTG 8                       // K chunks of 64 bf16

// ---- device scratch ----
__device__ __nv_bfloat16 g_xh[BSZ * DD];
__device__ __nv_bfloat16 g_xl[BSZ * DD];
__device__ __nv_bfloat16 g_ch[CC * DD];
__device__ __nv_bfloat16 g_cl[CC * DD];
__device__ float g_xnorm[BSZ];
__device__ float g_cnorm[CC];
__device__ int   g_present[CC];      // zero-init; only 1s written (idempotent across replays)
__device__ float g_minp[2 * BSZ];
__device__ float g_ownp[BSZ];
__device__ float g_rpart[64];
__device__ int   g_rcount;           // zero-init; reset by last block each call

// ---- smem layout (bytes) ----
#define SM_TILE 2048
#define OFF_AH  0
#define OFF_AL  16384
#define OFF_CH  32768
#define OFF_CL  65536
#define STG_B   98304
#define SMEM_BYTES (SM_TILE + 2 * STG_B)   // 198656

static __device__ __forceinline__ uint32_t s2u(const void* p) {
    uint32_t a;
    asm("{ .reg .u64 t; cvta.to.shared.u64 t, %1; cvt.u32.u64 %0, t; }" : "=r"(a) : "l"(p));
    return a;
}
static __device__ __forceinline__ void cp16(uint32_t dst, const void* src) {
    asm volatile("cp.async.cg.shared.global [%0], [%1], 16;" :: "r"(dst), "l"(src));
}
#define LDSM4(r0, r1, r2, r3, addr)                                             \
    asm volatile("ldmatrix.sync.aligned.m8n8.x4.shared.b16 {%0,%1,%2,%3}, [%4];" \
                 : "=r"(r0), "=r"(r1), "=r"(r2), "=r"(r3) : "r"(addr))
#define MMA(d, a, b0, b1)                                                        \
    asm volatile("mma.sync.aligned.m16n8k16.row.col.f32.bf16.bf16.f32 "          \
                 "{%0,%1,%2,%3},{%4,%5,%6,%7},{%8,%9},{%0,%1,%2,%3};"            \
                 : "+f"((d)[0]), "+f"((d)[1]), "+f"((d)[2]), "+f"((d)[3])        \
                 : "r"((a)[0]), "r"((a)[1]), "r"((a)[2]), "r"((a)[3]),           \
                   "r"(b0), "r"(b1))

// ---------------------------------------------------------------------------
// prep: f32 -> bf16 hi/lo split + row norms + class presence. One warp/row.
// ---------------------------------------------------------------------------
__global__ void prep_kernel(const float* __restrict__ X, const float* __restrict__ CT,
                            const int* __restrict__ T) {
    int row  = blockIdx.x * 8 + (threadIdx.x >> 5);
    int lane = threadIdx.x & 31;
    const float* src;
    __nv_bfloat16 *dh, *dl;
    float* nrm;
    size_t rb;
    if (row < CC) {
        src = CT + (size_t)row * DD; dh = g_ch; dl = g_cl; nrm = g_cnorm + row;
        rb = (size_t)row * DD;
    } else {
        int r = row - CC;
        if (r >= BSZ) return;
        src = X + (size_t)r * DD; dh = g_xh; dl = g_xl; nrm = g_xnorm + r;
        rb = (size_t)r * DD;
        if (lane == 0) g_present[T[r]] = 1;
    }
    float s = 0.f;
    const float4* p4 = (const float4*)src;
#pragma unroll
    for (int i = 0; i < 4; i++) {
        float4 v = p4[lane + 32 * i];
        s = fmaf(v.x, v.x, s); s = fmaf(v.y, v.y, s);
        s = fmaf(v.z, v.z, s); s = fmaf(v.w, v.w, s);
        __nv_bfloat16 hx = __float2bfloat16(v.x), hy = __float2bfloat16(v.y);
        __nv_bfloat16 hz = __float2bfloat16(v.z), hw = __float2bfloat16(v.w);
        __nv_bfloat16 lx = __float2bfloat16(v.x - __bfloat162float(hx));
        __nv_bfloat16 ly = __float2bfloat16(v.y - __bfloat162float(hy));
        __nv_bfloat16 lz = __float2bfloat16(v.z - __bfloat162float(hz));
        __nv_bfloat16 lw = __float2bfloat16(v.w - __bfloat162float(hw));
        uint2 hv, lv;
        hv.x = ((uint32_t)__bfloat16_as_ushort(hy) << 16) | __bfloat16_as_ushort(hx);
        hv.y = ((uint32_t)__bfloat16_as_ushort(hw) << 16) | __bfloat16_as_ushort(hz);
        lv.x = ((uint32_t)__bfloat16_as_ushort(ly) << 16) | __bfloat16_as_ushort(lx);
        lv.y = ((uint32_t)__bfloat16_as_ushort(lw) << 16) | __bfloat16_as_ushort(lz);
        size_t eo = rb + (size_t)(lane + 32 * i) * 4;
        *(uint2*)(dh + eo) = hv;
        *(uint2*)(dl + eo) = lv;
    }
#pragma unroll
    for (int o = 16; o > 0; o >>= 1) s += __shfl_xor_sync(0xffffffffu, s, o);
    if (lane == 0) *nrm = s;
}

// ---------------------------------------------------------------------------
// main: M128 x N256 bf16x3 HMMA GEMM + fused hardest-pos/neg epilogue.
// B-hi MMAs ordered ah0,ah1,al0,al1 (acc reuse distance 8); B-lo reuses the
// same 8 B registers (no extra pressure -> no spills).
// ---------------------------------------------------------------------------
__global__ __launch_bounds__(512, 1) void main_kernel(const int* __restrict__ T) {
    extern __shared__ char smem[];
    const uint32_t sb = s2u(smem);
    const int tid = threadIdx.x, lane = tid & 31, wid = tid >> 5;
    const int wr = wid >> 2, wc = wid & 3;
    const int mtile = blockIdx.x >> 1, nh = blockIdx.x & 1;
    const float INF = __int_as_float(0x7f800000);

    float* cn = (float*)smem;              // 256 floats
    int*   tg = (int*)(smem + 1024);       // 128 ints

    for (int i = tid; i < NT; i += 512) {
        int c = nh * NT + i;
        cn[i] = g_present[c] ? g_cnorm[c] : INF;
    }
    if (tid < MT) tg[tid] = T[mtile * MT + tid];

    // ---- cp.async stage loader: 768 rows x 128B, 12 x 16B chunks per thread ----
    const int trow_q = tid >> 3;           // 0..63 row-within-64 band
    const int tq     = tid & 7;            // 16B chunk within row
#define PREFETCH(ST)                                                              \
    do {                                                                          \
        const int st_ = (ST);                                                     \
        const uint32_t dstb_ = sb + SM_TILE + (uint32_t)(st_ & 1) * STG_B;        \
        _Pragma("unroll")                                                         \
        for (int i_ = 0; i_ < 12; i_++) {                                         \
            int row_ = i_ * 64 + trow_q;                                          \
            uint32_t off_ = (uint32_t)(row_ * 128 + tq * 16);                     \
            off_ ^= ((off_ >> 3) & 0x70);                                         \
            const __nv_bfloat16* s_;                                              \
            if (row_ < 128)      s_ = g_xh + (size_t)(mtile * MT + row_) * DD;    \
            else if (row_ < 256) s_ = g_xl + (size_t)(mtile * MT + row_ - 128) * DD; \
            else if (row_ < 512) s_ = g_ch + (size_t)(nh * NT + row_ - 256) * DD; \
            else                 s_ = g_cl + (size_t)(nh * NT + row_ - 512) * DD; \
            cp16(dstb_ + off_, s_ + st_ * 64 + tq * 8);                           \
        }                                                                         \
        asm volatile("cp.async.commit_group;");                                   \
    } while (0)

    PREFETCH(0);
    PREFETCH(1);

    float acc[2][8][4];
#pragma unroll
    for (int a = 0; a < 2; a++)
#pragma unroll
        for (int b = 0; b < 8; b++)
#pragma unroll
            for (int e = 0; e < 4; e++) acc[a][b][e] = 0.f;

    // fragment address components
    const int rA       = wr * 32 + (lane & 15);
    const uint32_t swz = (uint32_t)(lane & 7) << 4;        // swizzle XOR (row&7)<<4
    const uint32_t kA  = (uint32_t)(lane >> 4) << 4;       // A: 0/16B k offset
    const uint32_t kB  = (uint32_t)((lane >> 3) & 1) << 4; // B: 0/16B k offset
    const int nB       = ((lane >> 4) << 3) + (lane & 7);  // B row pattern 0..15

    for (int kt = 0; kt < NSTG; kt++) {
        if (kt == NSTG - 1) asm volatile("cp.async.wait_group 0;");
        else                asm volatile("cp.async.wait_group 1;");
        __syncthreads();

        const uint32_t tb   = sb + SM_TILE + (uint32_t)(kt & 1) * STG_B;
        const uint32_t aAh0 = tb + OFF_AH + (uint32_t)rA * 128;
        const uint32_t aAl0 = tb + OFF_AL + (uint32_t)rA * 128;

#pragma unroll
        for (int kk = 0; kk < 4; kk++) {
            const uint32_t ka = ((uint32_t)(kk * 32) + kA) ^ swz;
            const uint32_t kb = ((uint32_t)(kk * 32) + kB) ^ swz;
            uint32_t ah[2][4], al[2][4];
            LDSM4(ah[0][0], ah[0][1], ah[0][2], ah[0][3], aAh0 + ka);
            LDSM4(ah[1][0], ah[1][1], ah[1][2], ah[1][3], aAh0 + 16 * 128 + ka);
            LDSM4(al[0][0], al[0][1], al[0][2], al[0][3], aAl0 + ka);
            LDSM4(al[1][0], al[1][1], al[1][2], al[1][3], aAl0 + 16 * 128 + ka);
#pragma unroll
            for (int h = 0; h < 2; h++) {
                const uint32_t nbase = (uint32_t)(wc * 64 + h * 32 + nB) * 128;
                uint32_t b0[4], b1[4];
                // ---- B hi ----
                LDSM4(b0[0], b0[1], b0[2], b0[3], tb + OFF_CH + nbase + kb);
                LDSM4(b1[0], b1[1], b1[2], b1[3], tb + OFF_CH + nbase + 16 * 128 + kb);
                // ah0, ah1, al0, al1 — same-acc reuse distance = 8 issues
                MMA(acc[0][h * 4 + 0], ah[0], b0[0], b0[1]);
                MMA(acc[0][h * 4 + 1], ah[0], b0[2], b0[3]);
                MMA(acc[0][h * 4 + 2], ah[0], b1[0], b1[1]);
                MMA(acc[0][h * 4 + 3], ah[0], b1[2], b1[3]);
                MMA(acc[1][h * 4 + 0], ah[1], b0[0], b0[1]);
                MMA(acc[1][h * 4 + 1], ah[1], b0[2], b0[3]);
                MMA(acc[1][h * 4 + 2], ah[1], b1[0], b1[1]);
                MMA(acc[1][h * 4 + 3], ah[1], b1[2], b1[3]);
                MMA(acc[0][h * 4 + 0], al[0], b0[0], b0[1]);
                MMA(acc[0][h * 4 + 1], al[0], b0[2], b0[3]);
                MMA(acc[0][h * 4 + 2], al[0], b1[0], b1[1]);
                MMA(acc[0][h * 4 + 3], al[0], b1[2], b1[3]);
                MMA(acc[1][h * 4 + 0], al[1], b0[0], b0[1]);
                MMA(acc[1][h * 4 + 1], al[1], b0[2], b0[3]);
                MMA(acc[1][h * 4 + 2], al[1], b1[0], b1[1]);
                MMA(acc[1][h * 4 + 3], al[1], b1[2], b1[3]);
                // ---- B lo (reuse the same 8 B registers) ----
                LDSM4(b0[0], b0[1], b0[2], b0[3], tb + OFF_CL + nbase + kb);
                LDSM4(b1[0], b1[1], b1[2], b1[3], tb + OFF_CL + nbase + 16 * 128 + kb);
                MMA(acc[0][h * 4 + 0], ah[0], b0[0], b0[1]);
                MMA(acc[0][h * 4 + 1], ah[0], b0[2], b0[3]);
                MMA(acc[0][h * 4 + 2], ah[0], b1[0], b1[1]);
                MMA(acc[0][h * 4 + 3], ah[0], b1[2], b1[3]);
                MMA(acc[1][h * 4 + 0], ah[1], b0[0], b0[1]);
                MMA(acc[1][h * 4 + 1], ah[1], b0[2], b0[3]);
                MMA(acc[1][h * 4 + 2], ah[1], b1[0], b1[1]);
                MMA(acc[1][h * 4 + 3], ah[1], b1[2], b1[3]);
            }
        }
        __syncthreads();
        if (kt + 2 < NSTG) PREFETCH(kt + 2);
    }

    // ---- epilogue ----
    __syncthreads();                       // tiles now reusable as scratch
    float* red = (float*)(smem + SM_TILE);             // 128 x 4 floats
    float* own = (float*)(smem + SM_TILE + 2048);      // 128 floats

    float rmin[2][2];
#pragma unroll
    for (int mb = 0; mb < 2; mb++) { rmin[mb][0] = INF; rmin[mb][1] = INF; }

#pragma unroll
    for (int mb = 0; mb < 2; mb++)
#pragma unroll
        for (int j = 0; j < 8; j++) {
            const int colb = wc * 64 + (j >> 2) * 32 + (j & 3) * 8 + (lane & 3) * 2;
#pragma unroll
            for (int e = 0; e < 4; e++) {
                const int cl = colb + (e & 1);
                const int lr = wr * 32 + mb * 16 + ((e >> 1) << 3) + (lane >> 2);
                const float v = fmaf(-2.f, acc[mb][j][e], cn[cl]);
                const int oc = tg[lr] - nh * NT;
                if (cl == oc) own[lr] = v;
                else          rmin[mb][e >> 1] = fminf(rmin[mb][e >> 1], v);
            }
        }
#pragma unroll
    for (int mb = 0; mb < 2; mb++)
#pragma unroll
        for (int rr = 0; rr < 2; rr++) {
            float m = rmin[mb][rr];
            m = fminf(m, __shfl_xor_sync(0xffffffffu, m, 1));
            m = fminf(m, __shfl_xor_sync(0xffffffffu, m, 2));
            if ((lane & 3) == 0)
                red[(wr * 32 + mb * 16 + rr * 8 + (lane >> 2)) * 4 + wc] = m;
        }
    __syncthreads();

    if (tid < MT) {
        const int r = tid;
        float m = fminf(fminf(red[r * 4 + 0], red[r * 4 + 1]),
                        fminf(red[r * 4 + 2], red[r * 4 + 3]));
        const int grow = mtile * MT + r;
        g_minp[nh * BSZ + grow] = m;
        const int oc = tg[r] - nh * NT;
        if (oc >= 0 && oc < NT) g_ownp[grow] = own[r];
    }
#undef PREFETCH
}

// ---------------------------------------------------------------------------
// reduce + fused finish (atomic last-block pattern; deterministic, replay-safe)
// ---------------------------------------------------------------------------
__global__ void reduce_kernel(float* out, int out_size) {
    const int row = blockIdx.x * 256 + threadIdx.x;
    const int lane = threadIdx.x & 31, w = threadIdx.x >> 5;
    float mn  = fminf(g_minp[row], g_minp[BSZ + row]);
    float xn  = g_xnorm[row];
    float dap = sqrtf(fmaxf(xn + g_ownp[row], 1e-12f));
    float dan = sqrtf(fmaxf(xn + mn, 1e-12f));
    float li = fmaxf(0.f, dap - dan + 1.f);
    float pi = (dan > dap) ? 1.f : 0.f;
#pragma unroll
    for (int o = 16; o > 0; o >>= 1) {
        li += __shfl_xor_sync(0xffffffffu, li, o);
        pi += __shfl_xor_sync(0xffffffffu, pi, o);
    }
    __shared__ float sl[8], sp[8];
    __shared__ int slast;
    if (lane == 0) { sl[w] = li; sp[w] = pi; }
    __syncthreads();
    if (threadIdx.x == 0) {
        float a = 0.f, b = 0.f;
#pragma unroll
        for (int i = 0; i < 8; i++) { a += sl[i]; b += sp[i]; }
        g_rpart[2 * blockIdx.x]     = a;
        g_rpart[2 * blockIdx.x + 1] = b;
        __threadfence();
        slast = (atomicAdd(&g_rcount, 1) == (int)gridDim.x - 1);
    }
    __syncthreads();
    if (slast && threadIdx.x == 0) {
        float a = 0.f, b = 0.f;
        for (int i = 0; i < (int)gridDim.x; i++) {
            a += g_rpart[2 * i];
            b += g_rpart[2 * i + 1];
        }
        out[0] = a / (float)BSZ;
        if (out_size > 1) out[1] = b / (float)BSZ;
        g_rcount = 0;                 // reset for next graph replay
    }
}

// ---------------------------------------------------------------------------
extern "C" void kernel_launch(void* const* d_in, const int* in_sizes, int n_in,
                              void* d_out, int out_size) {
    const float* X  = nullptr;
    const float* CT = nullptr;
    const int*   T  = nullptr;
    for (int i = 0; i < n_in; i++) {
        if (in_sizes[i] == BSZ * DD)     X  = (const float*)d_in[i];
        else if (in_sizes[i] == CC * DD) CT = (const float*)d_in[i];
        else if (in_sizes[i] == BSZ)     T  = (const int*)d_in[i];
    }
    cudaFuncSetAttribute(main_kernel,
                         cudaFuncAttributeMaxDynamicSharedMemorySize, SMEM_BYTES);

    prep_kernel<<<(CC + BSZ) / 8, 256>>>(X, CT, T);
    main_kernel<<<2 * (BSZ / MT), 512, SMEM_BYTES>>>(T);
    reduce_kernel<<<BSZ / 256, 256>>>((float*)d_out, out_size);
}

// round 6
// speedup vs baseline: 1.6117x; 1.0806x over previous
#include <cuda_runtime.h>
#include <cuda_bf16.h>
#include <cstdint>

#define BSZ 8192
#define DD  512
#define CC  512
#define MT  128
#define NT  256
#define NSTG 8                  // K chunks of 64 bf16
#define TH  3.0f                // candidate threshold (>>10x max approx error)
#define SLOTS 16
#define RBLK 1024               // refine blocks

// ---- device scratch ----
__device__ __nv_bfloat16 g_xh[BSZ * DD];
__device__ __nv_bfloat16 g_ch[CC * DD];
__device__ float g_xnorm[BSZ];
__device__ float g_cnorm[CC];
__device__ int   g_present[CC];          // zero-init; only 1s written (idempotent)
__device__ unsigned short g_cand[BSZ * SLOTS];
__device__ int   g_cnt[BSZ];             // reset by prep each call
__device__ float g_rpart[2 * RBLK];
__device__ int   g_rcount;               // reset by last refine block

// ---- main kernel smem layout (bytes) ----
#define SM_CN     0
#define SM_TG     1024
#define SM_ROWMIN 1536
#define SM_TILE   2048
#define OFF_AH    0
#define OFF_CH    16384
#define STG_B     49152                  // 384 rows x 128B
#define SMEM_BYTES (SM_TILE + 2 * STG_B) // 100352

static __device__ __forceinline__ uint32_t s2u(const void* p) {
    uint32_t a;
    asm("{ .reg .u64 t; cvta.to.shared.u64 t, %1; cvt.u32.u64 %0, t; }" : "=r"(a) : "l"(p));
    return a;
}
static __device__ __forceinline__ void cp16(uint32_t dst, const void* src) {
    asm volatile("cp.async.cg.shared.global [%0], [%1], 16;" :: "r"(dst), "l"(src));
}
#define LDSM4(r0, r1, r2, r3, addr)                                             \
    asm volatile("ldmatrix.sync.aligned.m8n8.x4.shared.b16 {%0,%1,%2,%3}, [%4];" \
                 : "=r"(r0), "=r"(r1), "=r"(r2), "=r"(r3) : "r"(addr))
#define MMA(d, a, b0, b1)                                                        \
    asm volatile("mma.sync.aligned.m16n8k16.row.col.f32.bf16.bf16.f32 "          \
                 "{%0,%1,%2,%3},{%4,%5,%6,%7},{%8,%9},{%0,%1,%2,%3};"            \
                 : "+f"((d)[0]), "+f"((d)[1]), "+f"((d)[2]), "+f"((d)[3])        \
                 : "r"((a)[0]), "r"((a)[1]), "r"((a)[2]), "r"((a)[3]),           \
                   "r"(b0), "r"(b1))

// ---------------------------------------------------------------------------
// prep: f32 -> bf16 (round-nearest) + exact fp32 row norms + presence + cnt reset
// ---------------------------------------------------------------------------
__global__ void prep_kernel(const float* __restrict__ X, const float* __restrict__ CT,
                            const int* __restrict__ T) {
    int row  = blockIdx.x * 8 + (threadIdx.x >> 5);
    int lane = threadIdx.x & 31;
    const float* src;
    __nv_bfloat16* dh;
    float* nrm;
    size_t rb;
    if (row < CC) {
        src = CT + (size_t)row * DD; dh = g_ch; nrm = g_cnorm + row;
        rb = (size_t)row * DD;
    } else {
        int r = row - CC;
        if (r >= BSZ) return;
        src = X + (size_t)r * DD; dh = g_xh; nrm = g_xnorm + r;
        rb = (size_t)r * DD;
        if (lane == 0) { g_present[T[r]] = 1; g_cnt[r] = 0; }
    }
    float s = 0.f;
    const float4* p4 = (const float4*)src;
#pragma unroll
    for (int i = 0; i < 4; i++) {
        float4 v = p4[lane + 32 * i];
        s = fmaf(v.x, v.x, s); s = fmaf(v.y, v.y, s);
        s = fmaf(v.z, v.z, s); s = fmaf(v.w, v.w, s);
        uint2 hv;
        hv.x = ((uint32_t)__bfloat16_as_ushort(__float2bfloat16(v.y)) << 16)
             | __bfloat16_as_ushort(__float2bfloat16(v.x));
        hv.y = ((uint32_t)__bfloat16_as_ushort(__float2bfloat16(v.w)) << 16)
             | __bfloat16_as_ushort(__float2bfloat16(v.z));
        *(uint2*)(dh + rb + (size_t)(lane + 32 * i) * 4) = hv;
    }
#pragma unroll
    for (int o = 16; o > 0; o >>= 1) s += __shfl_xor_sync(0xffffffffu, s, o);
    if (lane == 0) *nrm = s;
}

// ---------------------------------------------------------------------------
// main: M128 x N256 single-product bf16 HMMA + approx-min + candidate marking.
// ---------------------------------------------------------------------------
__global__ __launch_bounds__(512, 1) void main_kernel(const int* __restrict__ T) {
    extern __shared__ char smem[];
    const uint32_t sb = s2u(smem);
    const int tid = threadIdx.x, lane = tid & 31, wid = tid >> 5;
    const int wr = wid >> 2, wc = wid & 3;
    const int mtile = blockIdx.x >> 1, nh = blockIdx.x & 1;
    const float INF = __int_as_float(0x7f800000);

    float* cn     = (float*)(smem + SM_CN);       // 256 floats
    int*   tg     = (int*)(smem + SM_TG);         // 128 ints
    float* rowmin = (float*)(smem + SM_ROWMIN);   // 128 floats

    for (int i = tid; i < NT; i += 512) {
        int c = nh * NT + i;
        cn[i] = g_present[c] ? g_cnorm[c] : INF;
    }
    if (tid < MT) tg[tid] = T[mtile * MT + tid];

    // ---- cp.async stage loader: 384 rows x 128B, 6 x 16B per thread ----
    const int trow_q = tid >> 3;           // 0..63
    const int tq     = tid & 7;
#define PREFETCH(ST)                                                              \
    do {                                                                          \
        const int st_ = (ST);                                                     \
        const uint32_t dstb_ = sb + SM_TILE + (uint32_t)(st_ & 1) * STG_B;        \
        _Pragma("unroll")                                                         \
        for (int i_ = 0; i_ < 6; i_++) {                                          \
            int row_ = i_ * 64 + trow_q;                                          \
            uint32_t off_ = (uint32_t)(row_ * 128 + tq * 16);                     \
            off_ ^= ((off_ >> 3) & 0x70);                                         \
            const __nv_bfloat16* s_;                                              \
            if (row_ < 128) s_ = g_xh + (size_t)(mtile * MT + row_) * DD;         \
            else            s_ = g_ch + (size_t)(nh * NT + row_ - 128) * DD;      \
            cp16(dstb_ + off_, s_ + st_ * 64 + tq * 8);                           \
        }                                                                         \
        asm volatile("cp.async.commit_group;");                                   \
    } while (0)

    PREFETCH(0);
    PREFETCH(1);

    float acc[2][8][4];
#pragma unroll
    for (int a = 0; a < 2; a++)
#pragma unroll
        for (int b = 0; b < 8; b++)
#pragma unroll
            for (int e = 0; e < 4; e++) acc[a][b][e] = 0.f;

    const int rA       = wr * 32 + (lane & 15);
    const uint32_t swz = (uint32_t)(lane & 7) << 4;
    const uint32_t kA  = (uint32_t)(lane >> 4) << 4;
    const uint32_t kB  = (uint32_t)((lane >> 3) & 1) << 4;
    const int nB       = ((lane >> 4) << 3) + (lane & 7);

    for (int kt = 0; kt < NSTG; kt++) {
        if (kt == NSTG - 1) asm volatile("cp.async.wait_group 0;");
        else                asm volatile("cp.async.wait_group 1;");
        __syncthreads();

        const uint32_t tb   = sb + SM_TILE + (uint32_t)(kt & 1) * STG_B;
        const uint32_t aAh0 = tb + OFF_AH + (uint32_t)rA * 128;

#pragma unroll
        for (int kk = 0; kk < 4; kk++) {
            const uint32_t ka = ((uint32_t)(kk * 32) + kA) ^ swz;
            const uint32_t kb = ((uint32_t)(kk * 32) + kB) ^ swz;
            uint32_t ah[2][4];
            LDSM4(ah[0][0], ah[0][1], ah[0][2], ah[0][3], aAh0 + ka);
            LDSM4(ah[1][0], ah[1][1], ah[1][2], ah[1][3], aAh0 + 16 * 128 + ka);
#pragma unroll
            for (int h = 0; h < 2; h++) {
                const uint32_t nbase = (uint32_t)(wc * 64 + h * 32 + nB) * 128;
                uint32_t b0[4], b1[4];
                LDSM4(b0[0], b0[1], b0[2], b0[3], tb + OFF_CH + nbase + kb);
                LDSM4(b1[0], b1[1], b1[2], b1[3], tb + OFF_CH + nbase + 16 * 128 + kb);
                MMA(acc[0][h * 4 + 0], ah[0], b0[0], b0[1]);
                MMA(acc[0][h * 4 + 1], ah[0], b0[2], b0[3]);
                MMA(acc[0][h * 4 + 2], ah[0], b1[0], b1[1]);
                MMA(acc[0][h * 4 + 3], ah[0], b1[2], b1[3]);
                MMA(acc[1][h * 4 + 0], ah[1], b0[0], b0[1]);
                MMA(acc[1][h * 4 + 1], ah[1], b0[2], b0[3]);
                MMA(acc[1][h * 4 + 2], ah[1], b1[0], b1[1]);
                MMA(acc[1][h * 4 + 3], ah[1], b1[2], b1[3]);
            }
        }
        __syncthreads();
        if (kt + 2 < NSTG) PREFETCH(kt + 2);
    }

    // ---- epilogue pass 1: approx row-min over non-own present classes ----
    __syncthreads();                        // tiles now dead
    float* red = (float*)(smem + SM_TILE);  // 128 x 4 floats

    float rmin[2][2];
#pragma unroll
    for (int mb = 0; mb < 2; mb++) { rmin[mb][0] = INF; rmin[mb][1] = INF; }

#pragma unroll
    for (int mb = 0; mb < 2; mb++)
#pragma unroll
        for (int j = 0; j < 8; j++) {
            const int colb = wc * 64 + (j >> 2) * 32 + (j & 3) * 8 + (lane & 3) * 2;
#pragma unroll
            for (int e = 0; e < 4; e++) {
                const int cl = colb + (e & 1);
                const int lr = wr * 32 + mb * 16 + ((e >> 1) << 3) + (lane >> 2);
                const float v = fmaf(-2.f, acc[mb][j][e], cn[cl]);
                const int oc = tg[lr] - nh * NT;
                if (cl != oc) rmin[mb][e >> 1] = fminf(rmin[mb][e >> 1], v);
            }
        }
#pragma unroll
    for (int mb = 0; mb < 2; mb++)
#pragma unroll
        for (int rr = 0; rr < 2; rr++) {
            float m = rmin[mb][rr];
            m = fminf(m, __shfl_xor_sync(0xffffffffu, m, 1));
            m = fminf(m, __shfl_xor_sync(0xffffffffu, m, 2));
            if ((lane & 3) == 0)
                red[(wr * 32 + mb * 16 + rr * 8 + (lane >> 2)) * 4 + wc] = m;
        }
    __syncthreads();
    if (tid < MT)
        rowmin[tid] = fminf(fminf(red[tid * 4 + 0], red[tid * 4 + 1]),
                            fminf(red[tid * 4 + 2], red[tid * 4 + 3]));
    __syncthreads();

    // ---- epilogue pass 2: mark candidates (v <= rowmin + TH, finite, non-own) ----
#pragma unroll
    for (int mb = 0; mb < 2; mb++)
#pragma unroll
        for (int j = 0; j < 8; j++) {
            const int colb = wc * 64 + (j >> 2) * 32 + (j & 3) * 8 + (lane & 3) * 2;
#pragma unroll
            for (int e = 0; e < 4; e++) {
                const int cl = colb + (e & 1);
                const int lr = wr * 32 + mb * 16 + ((e >> 1) << 3) + (lane >> 2);
                const float v = fmaf(-2.f, acc[mb][j][e], cn[cl]);
                const int oc = tg[lr] - nh * NT;
                if (cl != oc && v < 1.0e30f && v <= rowmin[lr] + TH) {
                    const int grow = mtile * MT + lr;
                    int s = atomicAdd(&g_cnt[grow], 1);
                    if (s < SLOTS)
                        g_cand[grow * SLOTS + s] = (unsigned short)(nh * NT + cl);
                }
            }
        }
#undef PREFETCH
}

// ---------------------------------------------------------------------------
// refine: exact fp32 dots for own + candidates, loss/prec, fused final reduce.
// One warp per row.
// ---------------------------------------------------------------------------
static __device__ __forceinline__ float dot512(const float4* xv, const float* crow, int lane) {
    const float4* c4 = (const float4*)crow;
    float s = 0.f;
#pragma unroll
    for (int i = 0; i < 4; i++) {
        float4 c = c4[lane + 32 * i];
        s = fmaf(xv[i].x, c.x, s); s = fmaf(xv[i].y, c.y, s);
        s = fmaf(xv[i].z, c.z, s); s = fmaf(xv[i].w, c.w, s);
    }
#pragma unroll
    for (int o = 16; o > 0; o >>= 1) s += __shfl_xor_sync(0xffffffffu, s, o);
    return s;
}

__global__ void refine_kernel(const float* __restrict__ X, const float* __restrict__ CT,
                              const int* __restrict__ T, float* out, int out_size) {
    const int w = threadIdx.x >> 5, lane = threadIdx.x & 31;
    const int row = blockIdx.x * 8 + w;
    const float INF = __int_as_float(0x7f800000);

    float4 xv[4];
    const float4* xr = (const float4*)(X + (size_t)row * DD);
#pragma unroll
    for (int i = 0; i < 4; i++) xv[i] = xr[lane + 32 * i];

    const int own = T[row];
    const float xn = g_xnorm[row];
    int cnt = g_cnt[row]; if (cnt > SLOTS) cnt = SLOTS;

    float dot_own = dot512(xv, CT + (size_t)own * DD, lane);
    float vmin = INF;
    for (int i = 0; i < cnt; i++) {
        int c = g_cand[row * SLOTS + i];
        if (c == own) continue;
        float d = dot512(xv, CT + (size_t)c * DD, lane);
        vmin = fminf(vmin, g_cnorm[c] - 2.f * d);
    }

    float dap = sqrtf(fmaxf(xn + g_cnorm[own] - 2.f * dot_own, 1e-12f));
    float dan = sqrtf(fmaxf(xn + vmin, 1e-12f));
    float li = fmaxf(0.f, dap - dan + 1.f);
    float pi = (dan > dap) ? 1.f : 0.f;

    __shared__ float sl[8], sp[8];
    __shared__ int slast;
    if (lane == 0) { sl[w] = li; sp[w] = pi; }
    __syncthreads();
    if (threadIdx.x == 0) {
        float a = 0.f, b = 0.f;
#pragma unroll
        for (int i = 0; i < 8; i++) { a += sl[i]; b += sp[i]; }
        g_rpart[2 * blockIdx.x]     = a;
        g_rpart[2 * blockIdx.x + 1] = b;
        __threadfence();
        slast = (atomicAdd(&g_rcount, 1) == (int)gridDim.x - 1);
    }
    __syncthreads();
    if (slast) {
        // 256 threads cooperatively sum 1024 partials (fixed order -> deterministic)
        const int t = threadIdx.x;
        float a = 0.f, b = 0.f;
#pragma unroll
        for (int k = 0; k < 4; k++) {
            a += g_rpart[2 * (t + 256 * k)];
            b += g_rpart[2 * (t + 256 * k) + 1];
        }
#pragma unroll
        for (int o = 16; o > 0; o >>= 1) {
            a += __shfl_xor_sync(0xffffffffu, a, o);
            b += __shfl_xor_sync(0xffffffffu, b, o);
        }
        __shared__ float fa[8], fb[8];
        if (lane == 0) { fa[w] = a; fb[w] = b; }
        __syncthreads();
        if (t == 0) {
            float sa = 0.f, sb = 0.f;
#pragma unroll
            for (int i = 0; i < 8; i++) { sa += fa[i]; sb += fb[i]; }
            out[0] = sa / (float)BSZ;
            if (out_size > 1) out[1] = sb / (float)BSZ;
            g_rcount = 0;            // reset for next graph replay
        }
    }
}

// ---------------------------------------------------------------------------
extern "C" void kernel_launch(void* const* d_in, const int* in_sizes, int n_in,
                              void* d_out, int out_size) {
    const float* X  = nullptr;
    const float* CT = nullptr;
    const int*   T  = nullptr;
    for (int i = 0; i < n_in; i++) {
        if (in_sizes[i] == BSZ * DD)     X  = (const float*)d_in[i];
        else if (in_sizes[i] == CC * DD) CT = (const float*)d_in[i];
        else if (in_sizes[i] == BSZ)     T  = (const int*)d_in[i];
    }
    cudaFuncSetAttribute(main_kernel,
                         cudaFuncAttributeMaxDynamicSharedMemorySize, SMEM_BYTES);

    prep_kernel<<<(CC + BSZ) / 8, 256>>>(X, CT, T);
    main_kernel<<<2 * (BSZ / MT), 512, SMEM_BYTES>>>(T);
    refine_kernel<<<RBLK, 256>>>(X, CT, T, (float*)d_out, out_size);
}

// round 7
// speedup vs baseline: 1.8550x; 1.1509x over previous
#include <cuda_runtime.h>
#include <cuda_bf16.h>
#include <cstdint>

#define BSZ 8192
#define DD  512
#define CC  512
#define MT  64                  // rows per CTA
#define NBLK (BSZ / MT)         // 128 CTAs
#define NSTG 8                  // K chunks of 64
#define TH  3.0f
#define SLOTS 16

// ---- device scratch ----
__device__ __nv_bfloat16 g_ch[CC * DD];
__device__ float g_cnorm[CC];
__device__ int   g_present[CC];      // zero-init; only 1s written (idempotent)
__device__ float g_rpart[2 * NBLK];
__device__ int   g_rcount;           // reset by last block each call

// ---- main smem layout (bytes) ----
#define SM_CN    0                   // 512 f
#define SM_TG    2048                // 64 i
#define SM_XN    2304                // 64 f
#define SM_RM    2560                // 64 f
#define SM_SCNT  2816                // 64 i
#define SM_CAND  3072                // 64*16 u16
#define SM_RED   5120                // 64*4 f
#define SM_LP    6144                // 64*2 f
#define SM_FIN   6656                // 8 f
#define SM_TILE  8192                // 1024-aligned
#define OFF_A    0                   // 64 rows x 128B
#define OFF_B    8192                // 512 rows x 128B
#define STG_B    73728
#define SMEM_BYTES (SM_TILE + 2 * STG_B)   // 155648

static __device__ __forceinline__ uint32_t s2u(const void* p) {
    uint32_t a;
    asm("{ .reg .u64 t; cvta.to.shared.u64 t, %1; cvt.u32.u64 %0, t; }" : "=r"(a) : "l"(p));
    return a;
}
static __device__ __forceinline__ void cp16(uint32_t dst, const void* src) {
    asm volatile("cp.async.cg.shared.global [%0], [%1], 16;" :: "r"(dst), "l"(src));
}
#define LDSM4(r0, r1, r2, r3, addr)                                             \
    asm volatile("ldmatrix.sync.aligned.m8n8.x4.shared.b16 {%0,%1,%2,%3}, [%4];" \
                 : "=r"(r0), "=r"(r1), "=r"(r2), "=r"(r3) : "r"(addr))
#define MMA(d, a, b0, b1)                                                        \
    asm volatile("mma.sync.aligned.m16n8k16.row.col.f32.bf16.bf16.f32 "          \
                 "{%0,%1,%2,%3},{%4,%5,%6,%7},{%8,%9},{%0,%1,%2,%3};"            \
                 : "+f"((d)[0]), "+f"((d)[1]), "+f"((d)[2]), "+f"((d)[3])        \
                 : "r"((a)[0]), "r"((a)[1]), "r"((a)[2]), "r"((a)[3]),           \
                   "r"(b0), "r"(b1))

static __device__ __forceinline__ uint32_t packbf(float x, float y) {
    return ((uint32_t)__bfloat16_as_ushort(__float2bfloat16(y)) << 16)
         | __bfloat16_as_ushort(__float2bfloat16(x));
}
static __device__ __forceinline__ uint4 cvt8(float4 a, float4 b) {
    uint4 r;
    r.x = packbf(a.x, a.y); r.y = packbf(a.z, a.w);
    r.z = packbf(b.x, b.y); r.w = packbf(b.z, b.w);
    return r;
}
static __device__ __forceinline__ float sq4(float4 v, float s) {
    s = fmaf(v.x, v.x, s); s = fmaf(v.y, v.y, s);
    s = fmaf(v.z, v.z, s); s = fmaf(v.w, v.w, s);
    return s;
}
static __device__ __forceinline__ float dot512(const float4* xv, const float* crow, int lane) {
    const float4* c4 = (const float4*)crow;
    float s = 0.f;
#pragma unroll
    for (int i = 0; i < 4; i++) {
        float4 c = c4[lane + 32 * i];
        s = fmaf(xv[i].x, c.x, s); s = fmaf(xv[i].y, c.y, s);
        s = fmaf(xv[i].z, c.z, s); s = fmaf(xv[i].w, c.w, s);
    }
#pragma unroll
    for (int o = 16; o > 0; o >>= 1) s += __shfl_xor_sync(0xffffffffu, s, o);
    return s;
}

// ---------------------------------------------------------------------------
// prep (small): centers f32->bf16 + cnorm (blocks 0..63); presence marks (64..67)
// ---------------------------------------------------------------------------
__global__ void prep_kernel(const float* __restrict__ CT, const int* __restrict__ T) {
    if (blockIdx.x >= 64) {
        int base = (blockIdx.x - 64) * 2048 + threadIdx.x;
#pragma unroll
        for (int k = 0; k < 8; k++) g_present[T[base + 256 * k]] = 1;
        return;
    }
    int row  = blockIdx.x * 8 + (threadIdx.x >> 5);
    int lane = threadIdx.x & 31;
    const float* src = CT + (size_t)row * DD;
    float s = 0.f;
    const float4* p4 = (const float4*)src;
#pragma unroll
    for (int i = 0; i < 4; i++) {
        float4 v = p4[lane + 32 * i];
        s = sq4(v, s);
        uint2 hv;
        hv.x = packbf(v.x, v.y);
        hv.y = packbf(v.z, v.w);
        *(uint2*)(g_ch + (size_t)row * DD + (size_t)(lane + 32 * i) * 4) = hv;
    }
#pragma unroll
    for (int o = 16; o > 0; o >>= 1) s += __shfl_xor_sync(0xffffffffu, s, o);
    if (lane == 0) g_cnorm[row] = s;
}

// ---------------------------------------------------------------------------
// main: fully fused. M64 x N512 bf16 HMMA (approx) + inline X conversion +
// row norms + candidate marking + exact fp32 refine + global reduction.
// ---------------------------------------------------------------------------
__global__ __launch_bounds__(512, 1) void main_kernel(
    const float* __restrict__ X, const float* __restrict__ CT,
    const int* __restrict__ T, float* out, int out_size)
{
    extern __shared__ char smem[];
    const uint32_t sb = s2u(smem);
    const int tid = threadIdx.x, lane = tid & 31, wid = tid >> 5;
    const int wr = wid >> 2, wc = wid & 3;
    const float INF = __int_as_float(0x7f800000);

    float* cn     = (float*)(smem + SM_CN);
    int*   tg     = (int*)(smem + SM_TG);
    float* sxn    = (float*)(smem + SM_XN);
    float* rowmin = (float*)(smem + SM_RM);
    int*   scnt   = (int*)(smem + SM_SCNT);
    unsigned short* scand = (unsigned short*)(smem + SM_CAND);
    float* red    = (float*)(smem + SM_RED);
    float* lp     = (float*)(smem + SM_LP);
    float* fin    = (float*)(smem + SM_FIN);

    {
        int c = tid;           // 512 threads, 512 classes
        cn[c] = g_present[c] ? g_cnorm[c] : INF;
    }
    if (tid < MT) { tg[tid] = T[blockIdx.x * MT + tid]; scnt[tid] = 0; }

    // ---- A producer state (f32 -> bf16 inline) ----
    const int arow = tid >> 3, aq = tid & 7;
    const float4* Ag = (const float4*)(X + (size_t)(blockIdx.x * MT + arow) * DD);
    const uint32_t aoff_sw = ((uint32_t)(arow * 128 + aq * 16))
                           ^ ((((uint32_t)(arow * 128 + aq * 16)) >> 3) & 0x70);
    float sq = 0.f;

    // ---- B producer indexing ----
    const int brow0 = tid >> 3, bq = tid & 7;
#define BFILL(ST)                                                                 \
    do {                                                                          \
        const int st_ = (ST);                                                     \
        const uint32_t dstb_ = sb + SM_TILE + (uint32_t)(st_ & 1) * STG_B + OFF_B;\
        _Pragma("unroll")                                                         \
        for (int i_ = 0; i_ < 8; i_++) {                                          \
            int row_ = brow0 + 64 * i_;                                           \
            uint32_t off_ = (uint32_t)(row_ * 128 + bq * 16);                     \
            off_ ^= ((off_ >> 3) & 0x70);                                         \
            cp16(dstb_ + off_, g_ch + (size_t)row_ * DD + st_ * 64 + bq * 8);     \
        }                                                                         \
        asm volatile("cp.async.commit_group;");                                   \
    } while (0)

    // ---- prologue: A(0), A(1) direct; B(0), B(1) async; A(2) into regs ----
#pragma unroll
    for (int st = 0; st < 2; st++) {
        float4 u0 = Ag[st * 16 + aq * 2], u1 = Ag[st * 16 + aq * 2 + 1];
        sq = sq4(u0, sq); sq = sq4(u1, sq);
        *(uint4*)(smem + SM_TILE + st * STG_B + OFF_A + aoff_sw) = cvt8(u0, u1);
    }
    BFILL(0);
    BFILL(1);
    float4 ar0 = Ag[2 * 16 + aq * 2], ar1 = Ag[2 * 16 + aq * 2 + 1];

    float acc[16][4];
#pragma unroll
    for (int j = 0; j < 16; j++)
#pragma unroll
        for (int e = 0; e < 4; e++) acc[j][e] = 0.f;

    const int rA       = wr * 16 + (lane & 15);
    const uint32_t swz = (uint32_t)(lane & 7) << 4;
    const uint32_t kA  = (uint32_t)(lane >> 4) << 4;
    const uint32_t kB  = (uint32_t)((lane >> 3) & 1) << 4;
    const int nB       = ((lane >> 4) << 3) + (lane & 7);

    for (int kt = 0; kt < NSTG; kt++) {
        if (kt == NSTG - 1) asm volatile("cp.async.wait_group 0;");
        else                asm volatile("cp.async.wait_group 1;");
        __syncthreads();

        const uint32_t tb  = sb + SM_TILE + (uint32_t)(kt & 1) * STG_B;
        const uint32_t aA0 = tb + OFF_A + (uint32_t)rA * 128;

#pragma unroll
        for (int kk = 0; kk < 4; kk++) {
            const uint32_t ka = ((uint32_t)(kk * 32) + kA) ^ swz;
            const uint32_t kb = ((uint32_t)(kk * 32) + kB) ^ swz;
            uint32_t a[4];
            LDSM4(a[0], a[1], a[2], a[3], aA0 + ka);
#pragma unroll
            for (int nb = 0; nb < 8; nb++) {
                const uint32_t baddr = tb + OFF_B
                    + (uint32_t)((wc * 128 + nb * 16 + nB) * 128) + kb;
                uint32_t b[4];
                LDSM4(b[0], b[1], b[2], b[3], baddr);
                MMA(acc[nb * 2 + 0], a, b[0], b[1]);
                MMA(acc[nb * 2 + 1], a, b[2], b[3]);
            }
        }
        __syncthreads();
        if (kt + 2 < NSTG) {
            // A(kt+2) from prefetched regs
            sq = sq4(ar0, sq); sq = sq4(ar1, sq);
            *(uint4*)(smem + SM_TILE + (size_t)(kt & 1) * STG_B + OFF_A + aoff_sw)
                = cvt8(ar0, ar1);
            BFILL(kt + 2);
            if (kt + 3 < NSTG) {
                ar0 = Ag[(kt + 3) * 16 + aq * 2];
                ar1 = Ag[(kt + 3) * 16 + aq * 2 + 1];
            }
        }
    }
#undef BFILL

    // ---- row norms: reduce over the 8 q-threads of each row ----
    sq += __shfl_xor_sync(0xffffffffu, sq, 1);
    sq += __shfl_xor_sync(0xffffffffu, sq, 2);
    sq += __shfl_xor_sync(0xffffffffu, sq, 4);
    if (aq == 0) sxn[arow] = sq;

    // ---- pass 1: approx row-min over non-own classes ----
    float rmin[2] = {INF, INF};
#pragma unroll
    for (int j = 0; j < 16; j++) {
        const int colb = wc * 128 + j * 8 + (lane & 3) * 2;
#pragma unroll
        for (int e = 0; e < 4; e++) {
            const int cl = colb + (e & 1);
            const int lr = wr * 16 + ((e >> 1) << 3) + (lane >> 2);
            const float v = fmaf(-2.f, acc[j][e], cn[cl]);
            if (cl != tg[lr]) rmin[e >> 1] = fminf(rmin[e >> 1], v);
        }
    }
#pragma unroll
    for (int rr = 0; rr < 2; rr++) {
        float m = rmin[rr];
        m = fminf(m, __shfl_xor_sync(0xffffffffu, m, 1));
        m = fminf(m, __shfl_xor_sync(0xffffffffu, m, 2));
        if ((lane & 3) == 0)
            red[(wr * 16 + rr * 8 + (lane >> 2)) * 4 + wc] = m;
    }
    __syncthreads();
    if (tid < MT)
        rowmin[tid] = fminf(fminf(red[tid * 4 + 0], red[tid * 4 + 1]),
                            fminf(red[tid * 4 + 2], red[tid * 4 + 3]));
    __syncthreads();

    // ---- pass 2: mark candidates ----
#pragma unroll
    for (int j = 0; j < 16; j++) {
        const int colb = wc * 128 + j * 8 + (lane & 3) * 2;
#pragma unroll
        for (int e = 0; e < 4; e++) {
            const int cl = colb + (e & 1);
            const int lr = wr * 16 + ((e >> 1) << 3) + (lane >> 2);
            const float v = fmaf(-2.f, acc[j][e], cn[cl]);
            if (cl != tg[lr] && v < 1.0e30f && v <= rowmin[lr] + TH) {
                int s = atomicAdd(&scnt[lr], 1);
                if (s < SLOTS) scand[lr * SLOTS + s] = (unsigned short)cl;
            }
        }
    }
    __syncthreads();

    // ---- refine: exact fp32 dots; warp w handles rows w*4..w*4+3 ----
#pragma unroll 1
    for (int rr = 0; rr < 4; rr++) {
        const int lr = wid * 4 + rr;
        const int grow = blockIdx.x * MT + lr;
        const float4* xr = (const float4*)(X + (size_t)grow * DD);
        float4 xv[4];
#pragma unroll
        for (int i = 0; i < 4; i++) xv[i] = xr[lane + 32 * i];
        const int own = tg[lr];
        const float dot_own = dot512(xv, CT + (size_t)own * DD, lane);
        int cnt = scnt[lr]; if (cnt > SLOTS) cnt = SLOTS;
        float vmin = INF;
        for (int i = 0; i < cnt; i++) {
            int c = scand[lr * SLOTS + i];
            float d = dot512(xv, CT + (size_t)c * DD, lane);
            vmin = fminf(vmin, cn[c] - 2.f * d);
        }
        const float xn = sxn[lr];
        float dap = sqrtf(fmaxf(xn + cn[own] - 2.f * dot_own, 1e-12f));
        float dan = sqrtf(fmaxf(xn + vmin, 1e-12f));
        if (lane == 0) {
            lp[2 * lr]     = fmaxf(0.f, dap - dan + 1.f);
            lp[2 * lr + 1] = (dan > dap) ? 1.f : 0.f;
        }
    }
    __syncthreads();

    // ---- per-CTA reduction + global last-block finish ----
    __shared__ int slast;
    if (tid < MT) {
        float li = lp[2 * tid], pi = lp[2 * tid + 1];
#pragma unroll
        for (int o = 16; o > 0; o >>= 1) {
            li += __shfl_xor_sync(0xffffffffu, li, o);
            pi += __shfl_xor_sync(0xffffffffu, pi, o);
        }
        if ((tid & 31) == 0) { fin[tid >> 5] = li; fin[4 + (tid >> 5)] = pi; }
    }
    __syncthreads();
    if (tid == 0) {
        g_rpart[2 * blockIdx.x]     = fin[0] + fin[1];
        g_rpart[2 * blockIdx.x + 1] = fin[4] + fin[5];
        __threadfence();
        slast = (atomicAdd(&g_rcount, 1) == NBLK - 1);
    }
    __syncthreads();
    if (slast) {
        float a = 0.f, b = 0.f;
        if (tid < NBLK) { a = g_rpart[2 * tid]; b = g_rpart[2 * tid + 1]; }
#pragma unroll
        for (int o = 16; o > 0; o >>= 1) {
            a += __shfl_xor_sync(0xffffffffu, a, o);
            b += __shfl_xor_sync(0xffffffffu, b, o);
        }
        if (tid < NBLK && (tid & 31) == 0) { fin[tid >> 5] = a; fin[4 + (tid >> 5)] = b; }
        __syncthreads();
        if (tid == 0) {
            float sa = fin[0] + fin[1] + fin[2] + fin[3];
            float sb = fin[4] + fin[5] + fin[6] + fin[7];
            out[0] = sa / (float)BSZ;
            if (out_size > 1) out[1] = sb / (float)BSZ;
            g_rcount = 0;            // reset for next graph replay
        }
    }
}

// ---------------------------------------------------------------------------
extern "C" void kernel_launch(void* const* d_in, const int* in_sizes, int n_in,
                              void* d_out, int out_size) {
    const float* X  = nullptr;
    const float* CT = nullptr;
    const int*   T  = nullptr;
    for (int i = 0; i < n_in; i++) {
        if (in_sizes[i] == BSZ * DD)     X  = (const float*)d_in[i];
        else if (in_sizes[i] == CC * DD) CT = (const float*)d_in[i];
        else if (in_sizes[i] == BSZ)     T  = (const int*)d_in[i];
    }
    cudaFuncSetAttribute(main_kernel,
                         cudaFuncAttributeMaxDynamicSharedMemorySize, SMEM_BYTES);

    prep_kernel<<<68, 256>>>(CT, T);
    main_kernel<<<NBLK, 512, SMEM_BYTES>>>(X, CT, T, (float*)d_out, out_size);
}

// round 8
// speedup vs baseline: 1.8949x; 1.0215x over previous
#include <cuda_runtime.h>
#include <cuda_bf16.h>
#include <cstdint>

#define BSZ 8192
#define DD  512
#define CC  512
#define MT  64                  // rows per CTA
#define NBLK (BSZ / MT)         // 128 CTAs
#define NSTG 8                  // K chunks of 64
#define TH  3.0f
#define SLOTS 16
#define NTH 1024

// ---- device scratch ----
__device__ __nv_bfloat16 g_ch[CC * DD];
__device__ float g_cnorm[CC];
__device__ int   g_present[CC];      // zero-init; only 1s written (idempotent)
__device__ float g_rpart[2 * NBLK];
__device__ int   g_rcount;           // reset by last block each call

// ---- main smem layout (bytes) ----
#define SM_CN    0                   // 512 f
#define SM_TG    2048                // 64 i
#define SM_XN    2304                // 64 f
#define SM_RM    2560                // 64 f
#define SM_SCNT  2816                // 64 i
#define SM_CAND  3072                // 64*16 u16
#define SM_RED   5120                // 64*8 f
#define SM_LP    7168                // 64*2 f
#define SM_FIN   7680                // 8 f
#define SM_TILE  8192                // 1024-aligned
#define OFF_A    0                   // 64 rows x 128B
#define OFF_B    8192                // 512 rows x 128B
#define STG_B    73728
#define SMEM_BYTES (SM_TILE + 2 * STG_B)   // 155648

static __device__ __forceinline__ uint32_t s2u(const void* p) {
    uint32_t a;
    asm("{ .reg .u64 t; cvta.to.shared.u64 t, %1; cvt.u32.u64 %0, t; }" : "=r"(a) : "l"(p));
    return a;
}
static __device__ __forceinline__ void cp16(uint32_t dst, const void* src) {
    asm volatile("cp.async.cg.shared.global [%0], [%1], 16;" :: "r"(dst), "l"(src));
}
#define LDSM4(r0, r1, r2, r3, addr)                                             \
    asm volatile("ldmatrix.sync.aligned.m8n8.x4.shared.b16 {%0,%1,%2,%3}, [%4];" \
                 : "=r"(r0), "=r"(r1), "=r"(r2), "=r"(r3) : "r"(addr))
#define MMA(d, a, b0, b1)                                                        \
    asm volatile("mma.sync.aligned.m16n8k16.row.col.f32.bf16.bf16.f32 "          \
                 "{%0,%1,%2,%3},{%4,%5,%6,%7},{%8,%9},{%0,%1,%2,%3};"            \
                 : "+f"((d)[0]), "+f"((d)[1]), "+f"((d)[2]), "+f"((d)[3])        \
                 : "r"((a)[0]), "r"((a)[1]), "r"((a)[2]), "r"((a)[3]),           \
                   "r"(b0), "r"(b1))

static __device__ __forceinline__ uint32_t packbf(float x, float y) {
    return ((uint32_t)__bfloat16_as_ushort(__float2bfloat16(y)) << 16)
         | __bfloat16_as_ushort(__float2bfloat16(x));
}
static __device__ __forceinline__ float sq4(float4 v, float s) {
    s = fmaf(v.x, v.x, s); s = fmaf(v.y, v.y, s);
    s = fmaf(v.z, v.z, s); s = fmaf(v.w, v.w, s);
    return s;
}
static __device__ __forceinline__ float dot512(const float4* xv, const float* crow, int lane) {
    const float4* c4 = (const float4*)crow;
    float s = 0.f;
#pragma unroll
    for (int i = 0; i < 4; i++) {
        float4 c = c4[lane + 32 * i];
        s = fmaf(xv[i].x, c.x, s); s = fmaf(xv[i].y, c.y, s);
        s = fmaf(xv[i].z, c.z, s); s = fmaf(xv[i].w, c.w, s);
    }
#pragma unroll
    for (int o = 16; o > 0; o >>= 1) s += __shfl_xor_sync(0xffffffffu, s, o);
    return s;
}

// ---------------------------------------------------------------------------
// prep (small): centers f32->bf16 + cnorm (blocks 0..63); presence marks (64..67)
// ---------------------------------------------------------------------------
__global__ void prep_kernel(const float* __restrict__ CT, const int* __restrict__ T) {
    if (blockIdx.x >= 64) {
        int base = (blockIdx.x - 64) * 2048 + threadIdx.x;
#pragma unroll
        for (int k = 0; k < 8; k++) g_present[T[base + 256 * k]] = 1;
        return;
    }
    int row  = blockIdx.x * 8 + (threadIdx.x >> 5);
    int lane = threadIdx.x & 31;
    const float* src = CT + (size_t)row * DD;
    float s = 0.f;
    const float4* p4 = (const float4*)src;
#pragma unroll
    for (int i = 0; i < 4; i++) {
        float4 v = p4[lane + 32 * i];
        s = sq4(v, s);
        uint2 hv;
        hv.x = packbf(v.x, v.y);
        hv.y = packbf(v.z, v.w);
        *(uint2*)(g_ch + (size_t)row * DD + (size_t)(lane + 32 * i) * 4) = hv;
    }
#pragma unroll
    for (int o = 16; o > 0; o >>= 1) s += __shfl_xor_sync(0xffffffffu, s, o);
    if (lane == 0) g_cnorm[row] = s;
}

// ---------------------------------------------------------------------------
// main: fully fused. 1024 threads, 32 warps (4 wr x 8 wc), warp tile m16 x n64.
// M64 x N512 bf16 HMMA (approx) + inline X conversion + row norms +
// candidate marking + exact fp32 refine + global reduction.
// ---------------------------------------------------------------------------
__global__ __launch_bounds__(NTH, 1) void main_kernel(
    const float* __restrict__ X, const float* __restrict__ CT,
    const int* __restrict__ T, float* out, int out_size)
{
    extern __shared__ char smem[];
    const uint32_t sb = s2u(smem);
    const int tid = threadIdx.x, lane = tid & 31, wid = tid >> 5;
    const int wr = wid >> 3, wc = wid & 7;
    const float INF = __int_as_float(0x7f800000);

    float* cn     = (float*)(smem + SM_CN);
    int*   tg     = (int*)(smem + SM_TG);
    float* sxn    = (float*)(smem + SM_XN);
    float* rowmin = (float*)(smem + SM_RM);
    int*   scnt   = (int*)(smem + SM_SCNT);
    unsigned short* scand = (unsigned short*)(smem + SM_CAND);
    float* red    = (float*)(smem + SM_RED);
    float* lp     = (float*)(smem + SM_LP);
    float* fin    = (float*)(smem + SM_FIN);

    if (tid < CC) cn[tid] = g_present[tid] ? g_cnorm[tid] : INF;
    if (tid < MT) { tg[tid] = T[blockIdx.x * MT + tid]; scnt[tid] = 0; }

    // ---- A producer: 64 rows x 16 threads; each converts one float4 -> uint2 ----
    const int arow = tid >> 4, aq = tid & 15;
    const float4* Ag = (const float4*)(X + (size_t)(blockIdx.x * MT + arow) * DD);
    const uint32_t aoff0 = (uint32_t)(arow * 128 + aq * 8);
    const uint32_t aoff_sw = aoff0 ^ ((aoff0 >> 3) & 0x70);
    float sq = 0.f;

    // ---- B producer: 512 rows x 8 chunks = 4096 cp16 / 1024 threads = 4 each ----
#define BFILL(ST)                                                                 \
    do {                                                                          \
        const int st_ = (ST);                                                     \
        const uint32_t dstb_ = sb + SM_TILE + (uint32_t)(st_ & 1) * STG_B + OFF_B;\
        _Pragma("unroll")                                                         \
        for (int i_ = 0; i_ < 4; i_++) {                                          \
            int idx_ = tid + i_ * NTH;                                            \
            int row_ = idx_ >> 3, q_ = idx_ & 7;                                  \
            uint32_t off_ = (uint32_t)(row_ * 128 + q_ * 16);                     \
            off_ ^= ((off_ >> 3) & 0x70);                                         \
            cp16(dstb_ + off_, g_ch + (size_t)row_ * DD + st_ * 64 + q_ * 8);     \
        }                                                                         \
        asm volatile("cp.async.commit_group;");                                   \
    } while (0)

    // ---- prologue ----
#pragma unroll
    for (int st = 0; st < 2; st++) {
        float4 u = Ag[st * 16 + aq];
        sq = sq4(u, sq);
        uint2 hv; hv.x = packbf(u.x, u.y); hv.y = packbf(u.z, u.w);
        *(uint2*)(smem + SM_TILE + st * STG_B + OFF_A + aoff_sw) = hv;
    }
    BFILL(0);
    BFILL(1);
    float4 ar = Ag[2 * 16 + aq];

    float acc[8][4];
#pragma unroll
    for (int j = 0; j < 8; j++)
#pragma unroll
        for (int e = 0; e < 4; e++) acc[j][e] = 0.f;

    const int rA       = wr * 16 + (lane & 15);
    const uint32_t swz = (uint32_t)(lane & 7) << 4;
    const uint32_t kA  = (uint32_t)(lane >> 4) << 4;
    const uint32_t kB  = (uint32_t)((lane >> 3) & 1) << 4;
    const int nB       = ((lane >> 4) << 3) + (lane & 7);

    for (int kt = 0; kt < NSTG; kt++) {
        if (kt == NSTG - 1) asm volatile("cp.async.wait_group 0;");
        else                asm volatile("cp.async.wait_group 1;");
        __syncthreads();

        const uint32_t tb    = sb + SM_TILE + (uint32_t)(kt & 1) * STG_B;
        const uint32_t aA0   = tb + OFF_A + (uint32_t)rA * 128;
        const uint32_t bbase = tb + OFF_B + (uint32_t)((wc * 64 + nB) * 128);

#pragma unroll
        for (int kk = 0; kk < 4; kk++) {
            const uint32_t ka = ((uint32_t)(kk * 32) + kA) ^ swz;
            const uint32_t kb = ((uint32_t)(kk * 32) + kB) ^ swz;
            uint32_t a[4];
            LDSM4(a[0], a[1], a[2], a[3], aA0 + ka);
#pragma unroll
            for (int nb = 0; nb < 4; nb++) {
                uint32_t b[4];
                LDSM4(b[0], b[1], b[2], b[3], bbase + (uint32_t)(nb * 2048) + kb);
                MMA(acc[nb * 2 + 0], a, b[0], b[1]);
                MMA(acc[nb * 2 + 1], a, b[2], b[3]);
            }
        }
        __syncthreads();
        if (kt + 2 < NSTG) {
            sq = sq4(ar, sq);
            uint2 hv; hv.x = packbf(ar.x, ar.y); hv.y = packbf(ar.z, ar.w);
            *(uint2*)(smem + SM_TILE + (size_t)(kt & 1) * STG_B + OFF_A + aoff_sw) = hv;
            BFILL(kt + 2);
            if (kt + 3 < NSTG) ar = Ag[(kt + 3) * 16 + aq];
        }
    }
#undef BFILL

    // ---- row norms: reduce over the 16 q-threads of each row ----
    sq += __shfl_xor_sync(0xffffffffu, sq, 1);
    sq += __shfl_xor_sync(0xffffffffu, sq, 2);
    sq += __shfl_xor_sync(0xffffffffu, sq, 4);
    sq += __shfl_xor_sync(0xffffffffu, sq, 8);
    if (aq == 0) sxn[arow] = sq;

    // ---- pass 1: approx row-min over non-own classes ----
    float rmin[2] = {INF, INF};
#pragma unroll
    for (int j = 0; j < 8; j++) {
        const int colb = wc * 64 + j * 8 + (lane & 3) * 2;
#pragma unroll
        for (int e = 0; e < 4; e++) {
            const int cl = colb + (e & 1);
            const int lr = wr * 16 + ((e >> 1) << 3) + (lane >> 2);
            const float v = fmaf(-2.f, acc[j][e], cn[cl]);
            if (cl != tg[lr]) rmin[e >> 1] = fminf(rmin[e >> 1], v);
        }
    }
#pragma unroll
    for (int rr = 0; rr < 2; rr++) {
        float m = rmin[rr];
        m = fminf(m, __shfl_xor_sync(0xffffffffu, m, 1));
        m = fminf(m, __shfl_xor_sync(0xffffffffu, m, 2));
        if ((lane & 3) == 0)
            red[(wr * 16 + rr * 8 + (lane >> 2)) * 8 + wc] = m;
    }
    __syncthreads();
    if (tid < MT) {
        float m = INF;
#pragma unroll
        for (int i = 0; i < 8; i++) m = fminf(m, red[tid * 8 + i]);
        rowmin[tid] = m;
    }
    __syncthreads();

    // ---- pass 2: mark candidates ----
#pragma unroll
    for (int j = 0; j < 8; j++) {
        const int colb = wc * 64 + j * 8 + (lane & 3) * 2;
#pragma unroll
        for (int e = 0; e < 4; e++) {
            const int cl = colb + (e & 1);
            const int lr = wr * 16 + ((e >> 1) << 3) + (lane >> 2);
            const float v = fmaf(-2.f, acc[j][e], cn[cl]);
            if (cl != tg[lr] && v < 1.0e30f && v <= rowmin[lr] + TH) {
                int s = atomicAdd(&scnt[lr], 1);
                if (s < SLOTS) scand[lr * SLOTS + s] = (unsigned short)cl;
            }
        }
    }
    __syncthreads();

    // ---- refine: exact fp32 dots; warp w handles rows w*2, w*2+1 ----
#pragma unroll 1
    for (int rr = 0; rr < 2; rr++) {
        const int lr = wid * 2 + rr;
        const int grow = blockIdx.x * MT + lr;
        const float4* xr = (const float4*)(X + (size_t)grow * DD);
        float4 xv[4];
#pragma unroll
        for (int i = 0; i < 4; i++) xv[i] = xr[lane + 32 * i];
        const int own = tg[lr];
        const float dot_own = dot512(xv, CT + (size_t)own * DD, lane);
        int cnt = scnt[lr]; if (cnt > SLOTS) cnt = SLOTS;
        float vmin = INF;
        for (int i = 0; i < cnt; i++) {
            int c = scand[lr * SLOTS + i];
            float d = dot512(xv, CT + (size_t)c * DD, lane);
            vmin = fminf(vmin, cn[c] - 2.f * d);
        }
        const float xn = sxn[lr];
        float dap = sqrtf(fmaxf(xn + cn[own] - 2.f * dot_own, 1e-12f));
        float dan = sqrtf(fmaxf(xn + vmin, 1e-12f));
        if (lane == 0) {
            lp[2 * lr]     = fmaxf(0.f, dap - dan + 1.f);
            lp[2 * lr + 1] = (dan > dap) ? 1.f : 0.f;
        }
    }
    __syncthreads();

    // ---- per-CTA reduction + global last-block finish ----
    __shared__ int slast;
    if (tid < MT) {
        float li = lp[2 * tid], pi = lp[2 * tid + 1];
#pragma unroll
        for (int o = 16; o > 0; o >>= 1) {
            li += __shfl_xor_sync(0xffffffffu, li, o);
            pi += __shfl_xor_sync(0xffffffffu, pi, o);
        }
        if ((tid & 31) == 0) { fin[tid >> 5] = li; fin[4 + (tid >> 5)] = pi; }
    }
    __syncthreads();
    if (tid == 0) {
        g_rpart[2 * blockIdx.x]     = fin[0] + fin[1];
        g_rpart[2 * blockIdx.x + 1] = fin[4] + fin[5];
        __threadfence();
        slast = (atomicAdd(&g_rcount, 1) == NBLK - 1);
    }
    __syncthreads();
    if (slast) {
        float a = 0.f, b = 0.f;
        if (tid < NBLK) { a = g_rpart[2 * tid]; b = g_rpart[2 * tid + 1]; }
#pragma unroll
        for (int o = 16; o > 0; o >>= 1) {
            a += __shfl_xor_sync(0xffffffffu, a, o);
            b += __shfl_xor_sync(0xffffffffu, b, o);
        }
        if (tid < NBLK && (tid & 31) == 0) { fin[tid >> 5] = a; fin[4 + (tid >> 5)] = b; }
        __syncthreads();
        if (tid == 0) {
            float sa = fin[0] + fin[1] + fin[2] + fin[3];
            float sb = fin[4] + fin[5] + fin[6] + fin[7];
            out[0] = sa / (float)BSZ;
            if (out_size > 1) out[1] = sb / (float)BSZ;
            g_rcount = 0;            // reset for next graph replay
        }
    }
}

// ---------------------------------------------------------------------------
extern "C" void kernel_launch(void* const* d_in, const int* in_sizes, int n_in,
                              void* d_out, int out_size) {
    const float* X  = nullptr;
    const float* CT = nullptr;
    const int*   T  = nullptr;
    for (int i = 0; i < n_in; i++) {
        if (in_sizes[i] == BSZ * DD)     X  = (const float*)d_in[i];
        else if (in_sizes[i] == CC * DD) CT = (const float*)d_in[i];
        else if (in_sizes[i] == BSZ)     T  = (const int*)d_in[i];
    }
    cudaFuncSetAttribute(main_kernel,
                         cudaFuncAttributeMaxDynamicSharedMemorySize, SMEM_BYTES);

    prep_kernel<<<68, 256>>>(CT, T);
    main_kernel<<<NBLK, NTH, SMEM_BYTES>>>(X, CT, T, (float*)d_out, out_size);
}

// round 9
// speedup vs baseline: 1.8998x; 1.0026x over previous
#include <cuda_runtime.h>
#include <cuda_bf16.h>
#include <cstdint>

#define BSZ 8192
#define DD  512
#define CC  512
#define MT  64                  // rows per CTA
#define NBLK (BSZ / MT)         // 128 CTAs
#define NSTG 8                  // K chunks of 64
#define TH  3.0f
#define SLOTS 16
#define NTH 512

// ---- device scratch ----
__device__ __nv_bfloat16 g_ch[CC * DD];
__device__ float g_cnorm[CC];
__device__ int   g_present[CC];      // zero-init; only 1s written (idempotent)
__device__ float g_rpart[2 * NBLK];
__device__ int   g_rcount;           // reset by last block each call

// ---- main smem layout (bytes) ----
#define SM_CN    0                   // 512 f
#define SM_TG    2048                // 64 i
#define SM_XN    2304                // 64 f
#define SM_RM    2560                // 64 f
#define SM_SCNT  2816                // 64 i
#define SM_CAND  3072                // 64*16 u16
#define SM_RED   5120                // 64*8 f
#define SM_LP    7168                // 64*2 f
#define SM_FIN   7680                // 8 f
#define SM_TILE  8192                // 1024-aligned
#define OFF_A    0                   // 64 rows x 128B
#define OFF_B    8192                // 512 rows x 128B
#define STG_B    73728
#define SMEM_BYTES (SM_TILE + 2 * STG_B)   // 155648

static __device__ __forceinline__ uint32_t s2u(const void* p) {
    uint32_t a;
    asm("{ .reg .u64 t; cvta.to.shared.u64 t, %1; cvt.u32.u64 %0, t; }" : "=r"(a) : "l"(p));
    return a;
}
static __device__ __forceinline__ void cp16(uint32_t dst, const void* src) {
    asm volatile("cp.async.cg.shared.global [%0], [%1], 16;" :: "r"(dst), "l"(src));
}
#define LDSM4(r0, r1, r2, r3, addr)                                             \
    asm volatile("ldmatrix.sync.aligned.m8n8.x4.shared.b16 {%0,%1,%2,%3}, [%4];" \
                 : "=r"(r0), "=r"(r1), "=r"(r2), "=r"(r3) : "r"(addr))
#define MMA(d, a, b0, b1)                                                        \
    asm volatile("mma.sync.aligned.m16n8k16.row.col.f32.bf16.bf16.f32 "          \
                 "{%0,%1,%2,%3},{%4,%5,%6,%7},{%8,%9},{%0,%1,%2,%3};"            \
                 : "+f"((d)[0]), "+f"((d)[1]), "+f"((d)[2]), "+f"((d)[3])        \
                 : "r"((a)[0]), "r"((a)[1]), "r"((a)[2]), "r"((a)[3]),           \
                   "r"(b0), "r"(b1))

static __device__ __forceinline__ uint32_t packbf(float x, float y) {
    return ((uint32_t)__bfloat16_as_ushort(__float2bfloat16(y)) << 16)
         | __bfloat16_as_ushort(__float2bfloat16(x));
}
static __device__ __forceinline__ uint4 cvt8(float4 a, float4 b) {
    uint4 r;
    r.x = packbf(a.x, a.y); r.y = packbf(a.z, a.w);
    r.z = packbf(b.x, b.y); r.w = packbf(b.z, b.w);
    return r;
}
static __device__ __forceinline__ float sq4(float4 v, float s) {
    s = fmaf(v.x, v.x, s); s = fmaf(v.y, v.y, s);
    s = fmaf(v.z, v.z, s); s = fmaf(v.w, v.w, s);
    return s;
}
static __device__ __forceinline__ float dot512(const float4* xv, const float* crow, int lane) {
    const float4* c4 = (const float4*)crow;
    float s = 0.f;
#pragma unroll
    for (int i = 0; i < 4; i++) {
        float4 c = c4[lane + 32 * i];
        s = fmaf(xv[i].x, c.x, s); s = fmaf(xv[i].y, c.y, s);
        s = fmaf(xv[i].z, c.z, s); s = fmaf(xv[i].w, c.w, s);
    }
#pragma unroll
    for (int o = 16; o > 0; o >>= 1) s += __shfl_xor_sync(0xffffffffu, s, o);
    return s;
}

// ---------------------------------------------------------------------------
// prep (small): centers f32->bf16 + cnorm (blocks 0..63); presence marks (64..67)
// ---------------------------------------------------------------------------
__global__ void prep_kernel(const float* __restrict__ CT, const int* __restrict__ T) {
    if (blockIdx.x >= 64) {
        int base = (blockIdx.x - 64) * 2048 + threadIdx.x;
#pragma unroll
        for (int k = 0; k < 8; k++) g_present[T[base + 256 * k]] = 1;
        return;
    }
    int row  = blockIdx.x * 8 + (threadIdx.x >> 5);
    int lane = threadIdx.x & 31;
    const float* src = CT + (size_t)row * DD;
    float s = 0.f;
    const float4* p4 = (const float4*)src;
#pragma unroll
    for (int i = 0; i < 4; i++) {
        float4 v = p4[lane + 32 * i];
        s = sq4(v, s);
        uint2 hv;
        hv.x = packbf(v.x, v.y);
        hv.y = packbf(v.z, v.w);
        *(uint2*)(g_ch + (size_t)row * DD + (size_t)(lane + 32 * i) * 4) = hv;
    }
#pragma unroll
    for (int o = 16; o > 0; o >>= 1) s += __shfl_xor_sync(0xffffffffu, s, o);
    if (lane == 0) g_cnorm[row] = s;
}

// ---------------------------------------------------------------------------
// main: fully fused. 512 threads, 16 warps (2 wr x 8 wc), warp tile m32 x n64
// (each B LDSM4 feeds 4 MMAs -> 40% less LDS traffic than m16n64).
// M64 x N512 bf16 HMMA (approx) + inline X conversion + row norms +
// candidate marking + exact fp32 refine + global reduction.
// ---------------------------------------------------------------------------
__global__ __launch_bounds__(NTH, 1) void main_kernel(
    const float* __restrict__ X, const float* __restrict__ CT,
    const int* __restrict__ T, float* out, int out_size)
{
    extern __shared__ char smem[];
    const uint32_t sb = s2u(smem);
    const int tid = threadIdx.x, lane = tid & 31, wid = tid >> 5;
    const int wr = wid >> 3, wc = wid & 7;
    const float INF = __int_as_float(0x7f800000);

    float* cn     = (float*)(smem + SM_CN);
    int*   tg     = (int*)(smem + SM_TG);
    float* sxn    = (float*)(smem + SM_XN);
    float* rowmin = (float*)(smem + SM_RM);
    int*   scnt   = (int*)(smem + SM_SCNT);
    unsigned short* scand = (unsigned short*)(smem + SM_CAND);
    float* red    = (float*)(smem + SM_RED);
    float* lp     = (float*)(smem + SM_LP);
    float* fin    = (float*)(smem + SM_FIN);

    if (tid < CC) cn[tid] = g_present[tid] ? g_cnorm[tid] : INF;
    if (tid < MT) { tg[tid] = T[blockIdx.x * MT + tid]; scnt[tid] = 0; }

    // ---- A producer: 64 rows x 8 threads; each converts 2 float4 -> uint4 ----
    const int arow = tid >> 3, aq = tid & 7;
    const float4* Ag = (const float4*)(X + (size_t)(blockIdx.x * MT + arow) * DD);
    const uint32_t aoff0 = (uint32_t)(arow * 128 + aq * 16);
    const uint32_t aoff_sw = aoff0 ^ ((aoff0 >> 3) & 0x70);
    float sq = 0.f;

    // ---- B producer: 512 rows x 8 chunks = 4096 cp16 / 512 threads = 8 each ----
    const int brow0 = tid >> 3, bq = tid & 7;
#define BFILL(ST)                                                                 \
    do {                                                                          \
        const int st_ = (ST);                                                     \
        const uint32_t dstb_ = sb + SM_TILE + (uint32_t)(st_ & 1) * STG_B + OFF_B;\
        _Pragma("unroll")                                                         \
        for (int i_ = 0; i_ < 8; i_++) {                                          \
            int row_ = brow0 + 64 * i_;                                           \
            uint32_t off_ = (uint32_t)(row_ * 128 + bq * 16);                     \
            off_ ^= ((off_ >> 3) & 0x70);                                         \
            cp16(dstb_ + off_, g_ch + (size_t)row_ * DD + st_ * 64 + bq * 8);     \
        }                                                                         \
        asm volatile("cp.async.commit_group;");                                   \
    } while (0)

    // ---- prologue ----
#pragma unroll
    for (int st = 0; st < 2; st++) {
        float4 u0 = Ag[st * 16 + aq * 2], u1 = Ag[st * 16 + aq * 2 + 1];
        sq = sq4(u0, sq); sq = sq4(u1, sq);
        *(uint4*)(smem + SM_TILE + st * STG_B + OFF_A + aoff_sw) = cvt8(u0, u1);
    }
    BFILL(0);
    BFILL(1);
    float4 ar0 = Ag[2 * 16 + aq * 2], ar1 = Ag[2 * 16 + aq * 2 + 1];

    float acc[2][8][4];
#pragma unroll
    for (int mb = 0; mb < 2; mb++)
#pragma unroll
        for (int j = 0; j < 8; j++)
#pragma unroll
            for (int e = 0; e < 4; e++) acc[mb][j][e] = 0.f;

    const int rA       = wr * 32 + (lane & 15);
    const uint32_t swz = (uint32_t)(lane & 7) << 4;
    const uint32_t kA  = (uint32_t)(lane >> 4) << 4;
    const uint32_t kB  = (uint32_t)((lane >> 3) & 1) << 4;
    const int nB       = ((lane >> 4) << 3) + (lane & 7);

    for (int kt = 0; kt < NSTG; kt++) {
        if (kt == NSTG - 1) asm volatile("cp.async.wait_group 0;");
        else                asm volatile("cp.async.wait_group 1;");
        __syncthreads();

        const uint32_t tb    = sb + SM_TILE + (uint32_t)(kt & 1) * STG_B;
        const uint32_t aA0   = tb + OFF_A + (uint32_t)rA * 128;
        const uint32_t bbase = tb + OFF_B + (uint32_t)((wc * 64 + nB) * 128);

#pragma unroll
        for (int kk = 0; kk < 4; kk++) {
            const uint32_t ka = ((uint32_t)(kk * 32) + kA) ^ swz;
            const uint32_t kb = ((uint32_t)(kk * 32) + kB) ^ swz;
            uint32_t ah[2][4];
            LDSM4(ah[0][0], ah[0][1], ah[0][2], ah[0][3], aA0 + ka);
            LDSM4(ah[1][0], ah[1][1], ah[1][2], ah[1][3], aA0 + 16 * 128 + ka);
#pragma unroll
            for (int nb = 0; nb < 4; nb++) {
                uint32_t b[4];
                LDSM4(b[0], b[1], b[2], b[3], bbase + (uint32_t)(nb * 2048) + kb);
                MMA(acc[0][nb * 2 + 0], ah[0], b[0], b[1]);
                MMA(acc[0][nb * 2 + 1], ah[0], b[2], b[3]);
                MMA(acc[1][nb * 2 + 0], ah[1], b[0], b[1]);
                MMA(acc[1][nb * 2 + 1], ah[1], b[2], b[3]);
            }
        }
        __syncthreads();
        if (kt + 2 < NSTG) {
            sq = sq4(ar0, sq); sq = sq4(ar1, sq);
            *(uint4*)(smem + SM_TILE + (size_t)(kt & 1) * STG_B + OFF_A + aoff_sw)
                = cvt8(ar0, ar1);
            BFILL(kt + 2);
            if (kt + 3 < NSTG) {
                ar0 = Ag[(kt + 3) * 16 + aq * 2];
                ar1 = Ag[(kt + 3) * 16 + aq * 2 + 1];
            }
        }
    }
#undef BFILL

    // ---- row norms: reduce over the 8 q-threads of each row ----
    sq += __shfl_xor_sync(0xffffffffu, sq, 1);
    sq += __shfl_xor_sync(0xffffffffu, sq, 2);
    sq += __shfl_xor_sync(0xffffffffu, sq, 4);
    if (aq == 0) sxn[arow] = sq;

    // ---- pass 1: approx row-min over non-own classes ----
    float rmin[2][2];
#pragma unroll
    for (int mb = 0; mb < 2; mb++) { rmin[mb][0] = INF; rmin[mb][1] = INF; }
#pragma unroll
    for (int mb = 0; mb < 2; mb++)
#pragma unroll
        for (int j = 0; j < 8; j++) {
            const int colb = wc * 64 + j * 8 + (lane & 3) * 2;
#pragma unroll
            for (int e = 0; e < 4; e++) {
                const int cl = colb + (e & 1);
                const int lr = wr * 32 + mb * 16 + ((e >> 1) << 3) + (lane >> 2);
                const float v = fmaf(-2.f, acc[mb][j][e], cn[cl]);
                if (cl != tg[lr]) rmin[mb][e >> 1] = fminf(rmin[mb][e >> 1], v);
            }
        }
#pragma unroll
    for (int mb = 0; mb < 2; mb++)
#pragma unroll
        for (int rr = 0; rr < 2; rr++) {
            float m = rmin[mb][rr];
            m = fminf(m, __shfl_xor_sync(0xffffffffu, m, 1));
            m = fminf(m, __shfl_xor_sync(0xffffffffu, m, 2));
            if ((lane & 3) == 0)
                red[(wr * 32 + mb * 16 + rr * 8 + (lane >> 2)) * 8 + wc] = m;
        }
    __syncthreads();
    if (tid < MT) {
        float m = INF;
#pragma unroll
        for (int i = 0; i < 8; i++) m = fminf(m, red[tid * 8 + i]);
        rowmin[tid] = m;
    }
    __syncthreads();

    // ---- pass 2: mark candidates ----
#pragma unroll
    for (int mb = 0; mb < 2; mb++)
#pragma unroll
        for (int j = 0; j < 8; j++) {
            const int colb = wc * 64 + j * 8 + (lane & 3) * 2;
#pragma unroll
            for (int e = 0; e < 4; e++) {
                const int cl = colb + (e & 1);
                const int lr = wr * 32 + mb * 16 + ((e >> 1) << 3) + (lane >> 2);
                const float v = fmaf(-2.f, acc[mb][j][e], cn[cl]);
                if (cl != tg[lr] && v < 1.0e30f && v <= rowmin[lr] + TH) {
                    int s = atomicAdd(&scnt[lr], 1);
                    if (s < SLOTS) scand[lr * SLOTS + s] = (unsigned short)cl;
                }
            }
        }
    __syncthreads();

    // ---- refine: exact fp32 dots; warp w handles rows w*4..w*4+3 ----
#pragma unroll 1
    for (int rr = 0; rr < 4; rr++) {
        const int lr = wid * 4 + rr;
        const int grow = blockIdx.x * MT + lr;
        const float4* xr = (const float4*)(X + (size_t)grow * DD);
        float4 xv[4];
#pragma unroll
        for (int i = 0; i < 4; i++) xv[i] = xr[lane + 32 * i];
        const int own = tg[lr];
        const float dot_own = dot512(xv, CT + (size_t)own * DD, lane);
        int cnt = scnt[lr]; if (cnt > SLOTS) cnt = SLOTS;
        float vmin = INF;
        for (int i = 0; i < cnt; i++) {
            int c = scand[lr * SLOTS + i];
            float d = dot512(xv, CT + (size_t)c * DD, lane);
            vmin = fminf(vmin, cn[c] - 2.f * d);
        }
        const float xn = sxn[lr];
        float dap = sqrtf(fmaxf(xn + cn[own] - 2.f * dot_own, 1e-12f));
        float dan = sqrtf(fmaxf(xn + vmin, 1e-12f));
        if (lane == 0) {
            lp[2 * lr]     = fmaxf(0.f, dap - dan + 1.f);
            lp[2 * lr + 1] = (dan > dap) ? 1.f : 0.f;
        }
    }
    __syncthreads();

    // ---- per-CTA reduction + global last-block finish ----
    __shared__ int slast;
    if (tid < MT) {
        float li = lp[2 * tid], pi = lp[2 * tid + 1];
#pragma unroll
        for (int o = 16; o > 0; o >>= 1) {
            li += __shfl_xor_sync(0xffffffffu, li, o);
            pi += __shfl_xor_sync(0xffffffffu, pi, o);
        }
        if ((tid & 31) == 0) { fin[tid >> 5] = li; fin[4 + (tid >> 5)] = pi; }
    }
    __syncthreads();
    if (tid == 0) {
        g_rpart[2 * blockIdx.x]     = fin[0] + fin[1];
        g_rpart[2 * blockIdx.x + 1] = fin[4] + fin[5];
        __threadfence();
        slast = (atomicAdd(&g_rcount, 1) == NBLK - 1);
    }
    __syncthreads();
    if (slast) {
        float a = 0.f, b = 0.f;
        if (tid < NBLK) { a = g_rpart[2 * tid]; b = g_rpart[2 * tid + 1]; }
#pragma unroll
        for (int o = 16; o > 0; o >>= 1) {
            a += __shfl_xor_sync(0xffffffffu, a, o);
            b += __shfl_xor_sync(0xffffffffu, b, o);
        }
        if (tid < NBLK && (tid & 31) == 0) { fin[tid >> 5] = a; fin[4 + (tid >> 5)] = b; }
        __syncthreads();
        if (tid == 0) {
            float sa = fin[0] + fin[1] + fin[2] + fin[3];
            float sb = fin[4] + fin[5] + fin[6] + fin[7];
            out[0] = sa / (float)BSZ;
            if (out_size > 1) out[1] = sb / (float)BSZ;
            g_rcount = 0;            // reset for next graph replay
        }
    }
}

// ---------------------------------------------------------------------------
extern "C" void kernel_launch(void* const* d_in, const int* in_sizes, int n_in,
                              void* d_out, int out_size) {
    const float* X  = nullptr;
    const float* CT = nullptr;
    const int*   T  = nullptr;
    for (int i = 0; i < n_in; i++) {
        if (in_sizes[i] == BSZ * DD)     X  = (const float*)d_in[i];
        else if (in_sizes[i] == CC * DD) CT = (const float*)d_in[i];
        else if (in_sizes[i] == BSZ)     T  = (const int*)d_in[i];
    }
    cudaFuncSetAttribute(main_kernel,
                         cudaFuncAttributeMaxDynamicSharedMemorySize, SMEM_BYTES);

    prep_kernel<<<68, 256>>>(CT, T);
    main_kernel<<<NBLK, NTH, SMEM_BYTES>>>(X, CT, T, (float*)d_out, out_size);
}